// round 1
// baseline (speedup 1.0000x reference)
#include <cuda_runtime.h>
#include <math.h>

#define BATCH  2
#define SEQ    2048
#define DMODEL 1024
#define NHEADS 16
#define DK     64
#define WIN    256

// -------- scratch (allocation-free rule: __device__ globals) --------
__device__ float g_q[BATCH * SEQ * DMODEL];
__device__ float g_k[BATCH * SEQ * DMODEL];
__device__ float g_v[BATCH * SEQ * DMODEL];
__device__ float g_ctx[BATCH * SEQ * DMODEL];

// ==================== GEMM: C = A @ W + bias ====================
// A: [M,K] row-major, W: [K,N] row-major, bias: [N], C: [M,N]
// 128x128 tile, BK=8, 256 threads, 8x8 per thread.
#define BM 128
#define BN 128
#define BK 8

__global__ __launch_bounds__(256)
void gemm_bias(const float* __restrict__ A, const float* __restrict__ W,
               const float* __restrict__ bias, float* __restrict__ C,
               int M, int N, int K) {
    __shared__ float As[BK][BM];
    __shared__ float Bs[BK][BN];

    const int brow = blockIdx.y * BM;
    const int bcol = blockIdx.x * BN;
    const int tid  = threadIdx.x;
    const int tr   = tid / 16;   // 0..15
    const int tc   = tid % 16;   // 0..15

    float acc[8][8];
    #pragma unroll
    for (int i = 0; i < 8; i++)
        #pragma unroll
        for (int j = 0; j < 8; j++) acc[i][j] = 0.f;

    // A-tile load mapping: 128 rows x 8 cols = 256 float4
    const int arow  = tid >> 1;          // 0..127
    const int acol4 = (tid & 1) * 4;     // 0 or 4
    // B-tile load mapping: 8 rows x 128 cols = 256 float4
    const int brw   = tid >> 5;          // 0..7
    const int bcol4 = (tid & 31) * 4;    // 0..124

    for (int k0 = 0; k0 < K; k0 += BK) {
        float4 av = *(const float4*)(A + (size_t)(brow + arow) * K + k0 + acol4);
        As[acol4 + 0][arow] = av.x;
        As[acol4 + 1][arow] = av.y;
        As[acol4 + 2][arow] = av.z;
        As[acol4 + 3][arow] = av.w;

        float4 bv = *(const float4*)(W + (size_t)(k0 + brw) * N + bcol + bcol4);
        *(float4*)&Bs[brw][bcol4] = bv;

        __syncthreads();

        #pragma unroll
        for (int kk = 0; kk < BK; kk++) {
            float a[8], b[8];
            #pragma unroll
            for (int i = 0; i < 8; i++) a[i] = As[kk][tr * 8 + i];
            #pragma unroll
            for (int j = 0; j < 8; j++) b[j] = Bs[kk][tc * 8 + j];
            #pragma unroll
            for (int i = 0; i < 8; i++)
                #pragma unroll
                for (int j = 0; j < 8; j++)
                    acc[i][j] += a[i] * b[j];
        }
        __syncthreads();
    }

    // epilogue with bias
    #pragma unroll
    for (int i = 0; i < 8; i++) {
        const int row = brow + tr * 8 + i;
        #pragma unroll
        for (int j0 = 0; j0 < 8; j0 += 4) {
            const int col = bcol + tc * 8 + j0;
            float4 o;
            o.x = acc[i][j0 + 0] + bias[col + 0];
            o.y = acc[i][j0 + 1] + bias[col + 1];
            o.z = acc[i][j0 + 2] + bias[col + 2];
            o.w = acc[i][j0 + 3] + bias[col + 3];
            *(float4*)(C + (size_t)row * N + col) = o;
        }
    }
}

// ==================== Sliding-window attention ====================
// One block (128 threads) per (b, h, q) row. Computes softmax over the
// band [q-WIN, q+WIN], writes the dense attn row (zeros outside band)
// into attnp (if non-null), and the context vector into g_ctx.
__global__ __launch_bounds__(128)
void attn_kernel(float* __restrict__ attnp) {
    const int r  = blockIdx.x;            // (b*H + h)*SEQ + q
    const int qi = r % SEQ;
    const int h  = (r / SEQ) % NHEADS;
    const int b  = r / (SEQ * NHEADS);
    const int tid = threadIdx.x;

    const int lo  = max(0, qi - WIN);
    const int hi  = min(SEQ - 1, qi + WIN);
    const int cnt = hi - lo + 1;          // <= 513

    __shared__ float sq[DK];
    __shared__ float sc[520];
    __shared__ float red[128];
    __shared__ float part[DK];

    // load q row into smem
    const float* qrow = g_q + (size_t)(b * SEQ + qi) * DMODEL + h * DK;
    if (tid < DK) sq[tid] = qrow[tid];
    __syncthreads();

    // ---- pass 1: scores + local max ----
    float lmax = -INFINITY;
    for (int idx = tid; idx < cnt; idx += 128) {
        const float* kr = g_k + (size_t)(b * SEQ + lo + idx) * DMODEL + h * DK;
        float dot = 0.f;
        #pragma unroll
        for (int d = 0; d < DK; d += 4) {
            float4 kv = *(const float4*)(kr + d);
            dot += sq[d] * kv.x + sq[d + 1] * kv.y + sq[d + 2] * kv.z + sq[d + 3] * kv.w;
        }
        float s = dot * 0.125f;           // 1/sqrt(64)
        sc[idx] = s;
        lmax = fmaxf(lmax, s);
    }
    red[tid] = lmax;
    __syncthreads();
    #pragma unroll
    for (int s = 64; s > 0; s >>= 1) {
        if (tid < s) red[tid] = fmaxf(red[tid], red[tid + s]);
        __syncthreads();
    }
    const float gmax = red[0];
    __syncthreads();

    // ---- pass 2: exp + sum ----
    float lsum = 0.f;
    for (int idx = tid; idx < cnt; idx += 128) {
        float e = expf(sc[idx] - gmax);
        sc[idx] = e;
        lsum += e;
    }
    red[tid] = lsum;
    __syncthreads();
    #pragma unroll
    for (int s = 64; s > 0; s >>= 1) {
        if (tid < s) red[tid] += red[tid + s];
        __syncthreads();
    }
    const float inv = 1.f / red[0];
    __syncthreads();

    // normalize in place
    for (int idx = tid; idx < cnt; idx += 128) sc[idx] *= inv;
    __syncthreads();

    // ---- dense attn row write (zeros outside band) ----
    if (attnp) {
        float* row = attnp + (size_t)r * SEQ;
        for (int c = tid; c < SEQ; c += 128) {
            float v = 0.f;
            if (c >= lo && c <= hi) v = sc[c - lo];
            row[c] = v;
        }
    }

    // ---- AV: out[d] = sum_j p_j * V[j,d]. 2 halves over keys x 64 dims ----
    const int half = tid >> 6;
    const int d    = tid & 63;
    float acc = 0.f;
    for (int idx = half; idx < cnt; idx += 2) {
        acc += sc[idx] * g_v[(size_t)(b * SEQ + lo + idx) * DMODEL + h * DK + d];
    }
    if (half == 1) part[d] = acc;
    __syncthreads();
    if (half == 0) {
        g_ctx[(size_t)(b * SEQ + qi) * DMODEL + h * DK + d] = acc + part[d];
    }
}

// ==================== launch ====================
extern "C" void kernel_launch(void* const* d_in, const int* in_sizes, int n_in,
                              void* d_out, int out_size) {
    const float* q  = (const float*)d_in[0];
    const float* k  = (const float*)d_in[1];
    const float* v  = (const float*)d_in[2];
    const float* Wq = (const float*)d_in[3];
    const float* bq = (const float*)d_in[4];
    const float* Wk = (const float*)d_in[5];
    const float* bk = (const float*)d_in[6];
    const float* Wv = (const float*)d_in[7];
    const float* bv = (const float*)d_in[8];
    const float* Wo = (const float*)d_in[9];
    const float* bo = (const float*)d_in[10];

    float *gq, *gk, *gv, *gctx;
    cudaGetSymbolAddress((void**)&gq,   g_q);
    cudaGetSymbolAddress((void**)&gk,   g_k);
    cudaGetSymbolAddress((void**)&gv,   g_v);
    cudaGetSymbolAddress((void**)&gctx, g_ctx);

    const int M = BATCH * SEQ;   // 4096
    const int N = DMODEL;        // 1024
    const int K = DMODEL;        // 1024
    dim3 ggrid(N / BN, M / BM);  // (8, 32)

    gemm_bias<<<ggrid, 256>>>(q, Wq, bq, gq, M, N, K);
    gemm_bias<<<ggrid, 256>>>(k, Wk, bk, gk, M, N, K);
    gemm_bias<<<ggrid, 256>>>(v, Wv, bv, gv, M, N, K);

    const size_t OUTE  = (size_t)BATCH * SEQ * DMODEL;                 // 4,194,304
    const size_t ATTNE = (size_t)BATCH * NHEADS * SEQ * SEQ;           // 134,217,728
    float* outp  = (float*)d_out;
    float* attnp = ((size_t)out_size >= OUTE + ATTNE) ? (outp + OUTE) : nullptr;

    attn_kernel<<<BATCH * NHEADS * SEQ, 128>>>(attnp);

    gemm_bias<<<ggrid, 256>>>(gctx, Wo, bo, outp, M, N, K);
}

// round 2
// speedup vs baseline: 2.4423x; 2.4423x over previous
#include <cuda_runtime.h>
#include <math.h>

#define BATCH  2
#define SEQ    2048
#define DMODEL 1024
#define NHEADS 16
#define DK     64
#define WIN    256

// -------- scratch (allocation-free rule: __device__ globals) --------
__device__ float g_q[BATCH * SEQ * DMODEL];
__device__ float g_k[BATCH * SEQ * DMODEL];
__device__ float g_v[BATCH * SEQ * DMODEL];
__device__ float g_ctx[BATCH * SEQ * DMODEL];

// ==================== GEMM: C = A @ W + bias ====================
// 128x128 tile, BK=16, 256 threads, 8x8 per thread, double-buffered smem.
__global__ __launch_bounds__(256, 2)
void gemm_bias(const float* __restrict__ A, const float* __restrict__ W,
               const float* __restrict__ bias, float* __restrict__ C,
               int M, int N, int K) {
    __shared__ float As[2][16][128];
    __shared__ float Bs[2][16][128];

    const int tid  = threadIdx.x;
    const int brow = blockIdx.y << 7;
    const int bcol = blockIdx.x << 7;
    const int tr   = tid >> 4;    // 0..15
    const int tc   = tid & 15;    // 0..15

    // A tile: 128 rows x 16 k -> 512 float4, 2 per thread (transposed store)
    const int ar0  = tid >> 2;            // rows 0..63
    const int ar1  = ar0 + 64;            // rows 64..127
    const int akc  = (tid & 3) << 2;      // k-col 0,4,8,12
    // B tile: 16 k x 128 cols -> 512 float4, 2 per thread (direct store)
    const int bk0  = tid >> 5;            // 0..7
    const int bk1  = bk0 + 8;             // 8..15
    const int bnc  = (tid & 31) << 2;     // 0..124

    float4 a0v, a1v, b0v, b1v;

    // prologue: tile 0
    a0v = *(const float4*)(A + (size_t)(brow + ar0) * K + akc);
    a1v = *(const float4*)(A + (size_t)(brow + ar1) * K + akc);
    b0v = *(const float4*)(W + (size_t)bk0 * N + bcol + bnc);
    b1v = *(const float4*)(W + (size_t)bk1 * N + bcol + bnc);
    As[0][akc + 0][ar0] = a0v.x; As[0][akc + 1][ar0] = a0v.y;
    As[0][akc + 2][ar0] = a0v.z; As[0][akc + 3][ar0] = a0v.w;
    As[0][akc + 0][ar1] = a1v.x; As[0][akc + 1][ar1] = a1v.y;
    As[0][akc + 2][ar1] = a1v.z; As[0][akc + 3][ar1] = a1v.w;
    *(float4*)&Bs[0][bk0][bnc] = b0v;
    *(float4*)&Bs[0][bk1][bnc] = b1v;
    __syncthreads();

    float acc[8][8];
    #pragma unroll
    for (int i = 0; i < 8; i++)
        #pragma unroll
        for (int j = 0; j < 8; j++) acc[i][j] = 0.f;

    const int nt = K >> 4;
    for (int kt = 0; kt < nt; kt++) {
        const int cur = kt & 1;
        if (kt + 1 < nt) {
            const int k0 = (kt + 1) << 4;
            a0v = *(const float4*)(A + (size_t)(brow + ar0) * K + k0 + akc);
            a1v = *(const float4*)(A + (size_t)(brow + ar1) * K + k0 + akc);
            b0v = *(const float4*)(W + (size_t)(k0 + bk0) * N + bcol + bnc);
            b1v = *(const float4*)(W + (size_t)(k0 + bk1) * N + bcol + bnc);
        }
        #pragma unroll
        for (int kk = 0; kk < 16; kk++) {
            float4 x0 = *(float4*)&As[cur][kk][tr * 8];
            float4 x1 = *(float4*)&As[cur][kk][tr * 8 + 4];
            float4 y0 = *(float4*)&Bs[cur][kk][tc * 8];
            float4 y1 = *(float4*)&Bs[cur][kk][tc * 8 + 4];
            float a[8] = {x0.x, x0.y, x0.z, x0.w, x1.x, x1.y, x1.z, x1.w};
            float b[8] = {y0.x, y0.y, y0.z, y0.w, y1.x, y1.y, y1.z, y1.w};
            #pragma unroll
            for (int i = 0; i < 8; i++)
                #pragma unroll
                for (int j = 0; j < 8; j++)
                    acc[i][j] += a[i] * b[j];
        }
        if (kt + 1 < nt) {
            const int nxt = cur ^ 1;
            As[nxt][akc + 0][ar0] = a0v.x; As[nxt][akc + 1][ar0] = a0v.y;
            As[nxt][akc + 2][ar0] = a0v.z; As[nxt][akc + 3][ar0] = a0v.w;
            As[nxt][akc + 0][ar1] = a1v.x; As[nxt][akc + 1][ar1] = a1v.y;
            As[nxt][akc + 2][ar1] = a1v.z; As[nxt][akc + 3][ar1] = a1v.w;
            *(float4*)&Bs[nxt][bk0][bnc] = b0v;
            *(float4*)&Bs[nxt][bk1][bnc] = b1v;
        }
        __syncthreads();
    }

    #pragma unroll
    for (int i = 0; i < 8; i++) {
        const int row = brow + tr * 8 + i;
        #pragma unroll
        for (int j0 = 0; j0 < 8; j0 += 4) {
            const int col = bcol + tc * 8 + j0;
            float4 o;
            o.x = acc[i][j0 + 0] + bias[col + 0];
            o.y = acc[i][j0 + 1] + bias[col + 1];
            o.z = acc[i][j0 + 2] + bias[col + 2];
            o.w = acc[i][j0 + 3] + bias[col + 3];
            *(float4*)(C + (size_t)row * N + col) = o;
        }
    }
}

// ==================== Tiled sliding-window attention ====================
// One block (256 thr) per (b, h, 64-query tile). K/V band processed in
// 64-key chunks through smem; full band scores kept in smem for exact
// softmax + dense attn write + AV.
#define TQ   64
#define QS   68    // sQ/sKV row stride (floats)
#define SSTR 584   // sS row stride (floats), >= 576, mult of 4

__global__ __launch_bounds__(256)
void attn_tile(float* __restrict__ attnp) {
    extern __shared__ float sm[];
    float* sQ  = sm;                  // 64 x 68
    float* sKV = sQ + 64 * QS;        // 64 x 68
    float* sS  = sKV + 64 * QS;       // 64 x 584

    const int qt = blockIdx.x, h = blockIdx.y, b = blockIdx.z;
    const int q0 = qt * TQ;
    const int tid = threadIdx.x;

    const int lo   = max(0, q0 - WIN);
    const int hi   = min(SEQ - 1, q0 + TQ - 1 + WIN);
    const int cnt  = hi - lo + 1;          // <= 576
    const int nch  = (cnt + 63) >> 6;
    const int npad = nch << 6;

    // ---- load Q tile ----
    {
        const float* base = g_q + ((size_t)(b * SEQ + q0)) * DMODEL + h * DK;
        for (int f = tid; f < 64 * 16; f += 256) {
            int r = f >> 4, c4 = (f & 15) << 2;
            float4 v = *(const float4*)(base + (size_t)r * DMODEL + c4);
            *(float4*)&sQ[r * QS + c4] = v;
        }
    }

    const int ty = tid >> 4, tx = tid & 15;

    // ---- pass 1: scores into sS ----
    for (int c = 0; c < nch; c++) {
        __syncthreads();
        const int kbase = lo + (c << 6);
        for (int f = tid; f < 64 * 16; f += 256) {
            int r = f >> 4, c4 = (f & 15) << 2;
            int kr = kbase + r;
            if (kr <= hi) {
                float4 v = *(const float4*)(g_k + ((size_t)(b * SEQ + kr)) * DMODEL + h * DK + c4);
                *(float4*)&sKV[r * QS + c4] = v;
            }
        }
        __syncthreads();

        float acc[4][4];
        #pragma unroll
        for (int i = 0; i < 4; i++)
            #pragma unroll
            for (int j = 0; j < 4; j++) acc[i][j] = 0.f;

        #pragma unroll
        for (int d = 0; d < 64; d += 4) {
            float4 qv[4], kv[4];
            #pragma unroll
            for (int i = 0; i < 4; i++) qv[i] = *(float4*)&sQ[(ty * 4 + i) * QS + d];
            #pragma unroll
            for (int jj = 0; jj < 4; jj++) kv[jj] = *(float4*)&sKV[(tx + jj * 16) * QS + d];
            #pragma unroll
            for (int i = 0; i < 4; i++)
                #pragma unroll
                for (int jj = 0; jj < 4; jj++)
                    acc[i][jj] += qv[i].x * kv[jj].x + qv[i].y * kv[jj].y
                                + qv[i].z * kv[jj].z + qv[i].w * kv[jj].w;
        }
        #pragma unroll
        for (int i = 0; i < 4; i++)
            #pragma unroll
            for (int jj = 0; jj < 4; jj++)
                sS[(ty * 4 + i) * SSTR + (c << 6) + tx + jj * 16] = acc[i][jj] * 0.125f;
    }
    __syncthreads();

    // ---- softmax (exact, band-masked); invalid entries -> 0 ----
    {
        const int warp = tid >> 5, lane = tid & 31;
        for (int m = warp; m < 64; m += 8) {
            const int qg  = q0 + m;
            const int jlo = max(lo, qg - WIN) - lo;
            const int jhi = min(hi, qg + WIN) - lo;
            float* row = sS + m * SSTR;

            float mx = -1e30f;
            for (int j = jlo + lane; j <= jhi; j += 32) mx = fmaxf(mx, row[j]);
            #pragma unroll
            for (int o = 16; o > 0; o >>= 1) mx = fmaxf(mx, __shfl_xor_sync(0xffffffffu, mx, o));

            float sum = 0.f;
            for (int j = lane; j < npad; j += 32) {
                float e = 0.f;
                if (j >= jlo && j <= jhi) e = __expf(row[j] - mx);
                row[j] = e;
                sum += e;
            }
            #pragma unroll
            for (int o = 16; o > 0; o >>= 1) sum += __shfl_xor_sync(0xffffffffu, sum, o);

            const float inv = 1.f / sum;
            for (int j = lane; j < npad; j += 32) row[j] *= inv;
        }
    }
    __syncthreads();

    // ---- dense attn write (zeros outside band) ----
    if (attnp) {
        float* base = attnp + ((size_t)((b * NHEADS + h) * SEQ + q0)) * SEQ;
        for (int f = tid; f < 64 * 512; f += 256) {
            int m = f >> 9, c4 = (f & 511) << 2;
            const float* row = sS + m * SSTR;
            float4 o;
            #pragma unroll
            for (int u = 0; u < 4; u++) {
                int cc = c4 + u;
                float v = 0.f;
                if (cc >= lo && cc <= hi) v = row[cc - lo];
                ((float*)&o)[u] = v;
            }
            *(float4*)(base + (size_t)m * SEQ + c4) = o;
        }
    }

    // ---- pass 2: AV ----
    float oacc[4][4];
    #pragma unroll
    for (int i = 0; i < 4; i++)
        #pragma unroll
        for (int u = 0; u < 4; u++) oacc[i][u] = 0.f;

    for (int c = 0; c < nch; c++) {
        __syncthreads();
        const int kbase = lo + (c << 6);
        for (int f = tid; f < 64 * 16; f += 256) {
            int r = f >> 4, c4 = (f & 15) << 2;
            int kr = kbase + r;
            if (kr <= hi) {
                float4 v = *(const float4*)(g_v + ((size_t)(b * SEQ + kr)) * DMODEL + h * DK + c4);
                *(float4*)&sKV[r * QS + c4] = v;
            }
        }
        __syncthreads();

        #pragma unroll 4
        for (int j = 0; j < 64; j += 4) {
            float4 p[4], vv[4];
            #pragma unroll
            for (int i = 0; i < 4; i++) p[i] = *(float4*)&sS[(ty * 4 + i) * SSTR + (c << 6) + j];
            #pragma unroll
            for (int jj = 0; jj < 4; jj++) vv[jj] = *(float4*)&sKV[(j + jj) * QS + tx * 4];
            #pragma unroll
            for (int i = 0; i < 4; i++) {
                #pragma unroll
                for (int u = 0; u < 4; u++) {
                    oacc[i][u] += ((float*)&p[i])[0] * ((float*)&vv[0])[u]
                                + ((float*)&p[i])[1] * ((float*)&vv[1])[u]
                                + ((float*)&p[i])[2] * ((float*)&vv[2])[u]
                                + ((float*)&p[i])[3] * ((float*)&vv[3])[u];
                }
            }
        }
    }

    // ---- write ctx ----
    {
        float* base = g_ctx + ((size_t)(b * SEQ + q0)) * DMODEL + h * DK;
        #pragma unroll
        for (int i = 0; i < 4; i++) {
            float4 o = make_float4(oacc[i][0], oacc[i][1], oacc[i][2], oacc[i][3]);
            *(float4*)(base + (size_t)(ty * 4 + i) * DMODEL + tx * 4) = o;
        }
    }
}

// ==================== launch ====================
extern "C" void kernel_launch(void* const* d_in, const int* in_sizes, int n_in,
                              void* d_out, int out_size) {
    const float* q  = (const float*)d_in[0];
    const float* k  = (const float*)d_in[1];
    const float* v  = (const float*)d_in[2];
    const float* Wq = (const float*)d_in[3];
    const float* bq = (const float*)d_in[4];
    const float* Wk = (const float*)d_in[5];
    const float* bk = (const float*)d_in[6];
    const float* Wv = (const float*)d_in[7];
    const float* bv = (const float*)d_in[8];
    const float* Wo = (const float*)d_in[9];
    const float* bo = (const float*)d_in[10];

    float *gq, *gk, *gv, *gctx;
    cudaGetSymbolAddress((void**)&gq,   g_q);
    cudaGetSymbolAddress((void**)&gk,   g_k);
    cudaGetSymbolAddress((void**)&gv,   g_v);
    cudaGetSymbolAddress((void**)&gctx, g_ctx);

    const int M = BATCH * SEQ;   // 4096
    const int N = DMODEL;        // 1024
    const int K = DMODEL;        // 1024
    dim3 ggrid(N / 128, M / 128);

    const int ATTN_SMEM = (64 * QS * 2 + 64 * SSTR) * sizeof(float);  // 184320 B
    static int smem_set = 0;
    if (!smem_set) {
        cudaFuncSetAttribute(attn_tile, cudaFuncAttributeMaxDynamicSharedMemorySize, ATTN_SMEM);
        smem_set = 1;
    }

    gemm_bias<<<ggrid, 256>>>(q, Wq, bq, gq, M, N, K);
    gemm_bias<<<ggrid, 256>>>(k, Wk, bk, gk, M, N, K);
    gemm_bias<<<ggrid, 256>>>(v, Wv, bv, gv, M, N, K);

    const size_t OUTE  = (size_t)BATCH * SEQ * DMODEL;
    const size_t ATTNE = (size_t)BATCH * NHEADS * SEQ * SEQ;
    float* outp  = (float*)d_out;
    float* attnp = ((size_t)out_size >= OUTE + ATTNE) ? (outp + OUTE) : nullptr;

    dim3 agrid(SEQ / TQ, NHEADS, BATCH);
    attn_tile<<<agrid, 256, ATTN_SMEM>>>(attnp);

    gemm_bias<<<ggrid, 256>>>(gctx, Wo, bo, outp, M, N, K);
}

// round 3
// speedup vs baseline: 2.7929x; 1.1436x over previous
#include <cuda_runtime.h>
#include <math.h>

#define BATCH  2
#define SEQ    2048
#define DMODEL 1024
#define NHEADS 16
#define DK     64
#define WIN    256

// -------- scratch (allocation-free rule: __device__ globals) --------
__device__ float g_q[BATCH * SEQ * DMODEL];
__device__ float g_k[BATCH * SEQ * DMODEL];
__device__ float g_v[BATCH * SEQ * DMODEL];
__device__ float g_ctx[BATCH * SEQ * DMODEL];

// -------- f32x2 packed-FMA helpers (Blackwell FFMA2) --------
__device__ __forceinline__ unsigned long long pack_dup(float a) {
    unsigned long long r;
    asm("mov.b64 %0, {%1, %1};" : "=l"(r) : "f"(a));
    return r;
}
__device__ __forceinline__ void ffma2(unsigned long long& d,
                                      unsigned long long a,
                                      unsigned long long b) {
    asm("fma.rn.f32x2 %0, %1, %2, %0;" : "+l"(d) : "l"(a), "l"(b));
}
__device__ __forceinline__ float2 unpk(unsigned long long v) {
    float2 f;
    asm("mov.b64 {%0, %1}, %2;" : "=f"(f.x), "=f"(f.y) : "l"(v));
    return f;
}

// ==================== GEMM: C = A @ W + bias (f32x2 inner) ====================
// 128x128 tile, BK=16, 256 threads, 8x8 per thread, double-buffered smem.
struct QKVArgs {
    const float* A[3];
    const float* W[3];
    const float* bias[3];
    float*       C[3];
};

__device__ __forceinline__
void gemm_body(const float* __restrict__ A, const float* __restrict__ W,
               const float* __restrict__ bias, float* __restrict__ C,
               float As[2][16][128], float Bs[2][16][128]) {
    const int K = DMODEL, N = DMODEL;
    const int tid  = threadIdx.x;
    const int brow = blockIdx.y << 7;
    const int bcol = blockIdx.x << 7;
    const int tr   = tid >> 4;
    const int tc   = tid & 15;

    const int ar0  = tid >> 2;
    const int ar1  = ar0 + 64;
    const int akc  = (tid & 3) << 2;
    const int bk0  = tid >> 5;
    const int bk1  = bk0 + 8;
    const int bnc  = (tid & 31) << 2;

    float4 a0v, a1v, b0v, b1v;

    a0v = *(const float4*)(A + (size_t)(brow + ar0) * K + akc);
    a1v = *(const float4*)(A + (size_t)(brow + ar1) * K + akc);
    b0v = *(const float4*)(W + (size_t)bk0 * N + bcol + bnc);
    b1v = *(const float4*)(W + (size_t)bk1 * N + bcol + bnc);
    As[0][akc + 0][ar0] = a0v.x; As[0][akc + 1][ar0] = a0v.y;
    As[0][akc + 2][ar0] = a0v.z; As[0][akc + 3][ar0] = a0v.w;
    As[0][akc + 0][ar1] = a1v.x; As[0][akc + 1][ar1] = a1v.y;
    As[0][akc + 2][ar1] = a1v.z; As[0][akc + 3][ar1] = a1v.w;
    *(float4*)&Bs[0][bk0][bnc] = b0v;
    *(float4*)&Bs[0][bk1][bnc] = b1v;
    __syncthreads();

    unsigned long long acc2[8][4];
    #pragma unroll
    for (int i = 0; i < 8; i++)
        #pragma unroll
        for (int j = 0; j < 4; j++) acc2[i][j] = 0ull;

    const int nt = K >> 4;
    for (int kt = 0; kt < nt; kt++) {
        const int cur = kt & 1;
        if (kt + 1 < nt) {
            const int k0 = (kt + 1) << 4;
            a0v = *(const float4*)(A + (size_t)(brow + ar0) * K + k0 + akc);
            a1v = *(const float4*)(A + (size_t)(brow + ar1) * K + k0 + akc);
            b0v = *(const float4*)(W + (size_t)(k0 + bk0) * N + bcol + bnc);
            b1v = *(const float4*)(W + (size_t)(k0 + bk1) * N + bcol + bnc);
        }
        #pragma unroll
        for (int kk = 0; kk < 16; kk++) {
            float4 x0 = *(float4*)&As[cur][kk][tr * 8];
            float4 x1 = *(float4*)&As[cur][kk][tr * 8 + 4];
            ulonglong2 y0 = *(ulonglong2*)&Bs[cur][kk][tc * 8];
            ulonglong2 y1 = *(ulonglong2*)&Bs[cur][kk][tc * 8 + 4];
            float a[8] = {x0.x, x0.y, x0.z, x0.w, x1.x, x1.y, x1.z, x1.w};
            #pragma unroll
            for (int i = 0; i < 8; i++) {
                unsigned long long ad = pack_dup(a[i]);
                ffma2(acc2[i][0], ad, y0.x);
                ffma2(acc2[i][1], ad, y0.y);
                ffma2(acc2[i][2], ad, y1.x);
                ffma2(acc2[i][3], ad, y1.y);
            }
        }
        if (kt + 1 < nt) {
            const int nxt = cur ^ 1;
            As[nxt][akc + 0][ar0] = a0v.x; As[nxt][akc + 1][ar0] = a0v.y;
            As[nxt][akc + 2][ar0] = a0v.z; As[nxt][akc + 3][ar0] = a0v.w;
            As[nxt][akc + 0][ar1] = a1v.x; As[nxt][akc + 1][ar1] = a1v.y;
            As[nxt][akc + 2][ar1] = a1v.z; As[nxt][akc + 3][ar1] = a1v.w;
            *(float4*)&Bs[nxt][bk0][bnc] = b0v;
            *(float4*)&Bs[nxt][bk1][bnc] = b1v;
        }
        __syncthreads();
    }

    float4 bb0 = *(const float4*)(bias + bcol + tc * 8);
    float4 bb1 = *(const float4*)(bias + bcol + tc * 8 + 4);
    #pragma unroll
    for (int i = 0; i < 8; i++) {
        const int row = brow + tr * 8 + i;
        const int col = bcol + tc * 8;
        float2 p0 = unpk(acc2[i][0]);
        float2 p1 = unpk(acc2[i][1]);
        float2 p2 = unpk(acc2[i][2]);
        float2 p3 = unpk(acc2[i][3]);
        float4 o0 = make_float4(p0.x + bb0.x, p0.y + bb0.y, p1.x + bb0.z, p1.y + bb0.w);
        float4 o1 = make_float4(p2.x + bb1.x, p2.y + bb1.y, p3.x + bb1.z, p3.y + bb1.w);
        *(float4*)(C + (size_t)row * DMODEL + col)     = o0;
        *(float4*)(C + (size_t)row * DMODEL + col + 4) = o1;
    }
}

__global__ __launch_bounds__(256, 2)
void gemm_qkv(QKVArgs args) {
    __shared__ float As[2][16][128];
    __shared__ float Bs[2][16][128];
    const int z = blockIdx.z;
    gemm_body(args.A[z], args.W[z], args.bias[z], args.C[z], As, Bs);
}

__global__ __launch_bounds__(256, 2)
void gemm_single(const float* __restrict__ A, const float* __restrict__ W,
                 const float* __restrict__ bias, float* __restrict__ C) {
    __shared__ float As[2][16][128];
    __shared__ float Bs[2][16][128];
    gemm_body(A, W, bias, C, As, Bs);
}

// ==================== Tiled sliding-window attention ====================
// 512 threads per block, 64 queries per block, 128-key chunks.
#define TQ   64
#define CH   128
#define QS   68     // sQ row stride
#define VS   132    // sVT row stride (d-major V transpose)
#define SSTR 644    // sS row stride (>= 5*128, 16B-aligned rows)

__global__ __launch_bounds__(512)
void attn_tile(float* __restrict__ attnp) {
    extern __shared__ float sm[];
    float* sQ  = sm;                 // 64 x 68   = 4352 floats
    float* sKV = sQ + 64 * QS;       // 8704 floats (K: 128x68 / VT: 64x132)
    float* sS  = sKV + CH * QS;      // 64 x 644

    const int qt = blockIdx.x, h = blockIdx.y, b = blockIdx.z;
    const int q0 = qt * TQ;
    const int tid = threadIdx.x;

    const int lo   = max(0, q0 - WIN);
    const int hi   = min(SEQ - 1, q0 + TQ - 1 + WIN);
    const int cnt  = hi - lo + 1;               // <= 576
    const int nch  = (cnt + CH - 1) / CH;       // <= 5
    const int npad = nch * CH;

    // ---- load Q tile ----
    {
        const float* base = g_q + ((size_t)(b * SEQ + q0)) * DMODEL + h * DK;
        #pragma unroll
        for (int it = 0; it < 2; it++) {
            int f = tid + it * 512;
            int r = f >> 4, c4 = (f & 15) << 2;
            *(float4*)&sQ[r * QS + c4] = *(const float4*)(base + (size_t)r * DMODEL + c4);
        }
    }

    // ---- pass 1: scores (f32x2 packed over d) ----
    const int tq  = tid >> 5;        // 0..15 -> q rows [tq*4, tq*4+4)
    const int tx  = tid & 31;        // k cols {tx + 32*jj}
    for (int c = 0; c < nch; c++) {
        const int kbase = lo + c * CH;
        __syncthreads();
        #pragma unroll
        for (int it = 0; it < 4; it++) {
            int f = tid + it * 512;
            int r = f >> 4, c4 = (f & 15) << 2;
            int kr = kbase + r;
            float4 v = make_float4(0.f, 0.f, 0.f, 0.f);
            if (kr <= hi) v = *(const float4*)(g_k + ((size_t)(b * SEQ + kr)) * DMODEL + h * DK + c4);
            *(float4*)&sKV[r * QS + c4] = v;
        }
        __syncthreads();

        unsigned long long acc2[4][4];
        #pragma unroll
        for (int i = 0; i < 4; i++)
            #pragma unroll
            for (int j = 0; j < 4; j++) acc2[i][j] = 0ull;

        #pragma unroll
        for (int d = 0; d < 64; d += 4) {
            ulonglong2 qv[4];
            #pragma unroll
            for (int i = 0; i < 4; i++)
                qv[i] = *(ulonglong2*)&sQ[(tq * 4 + i) * QS + d];
            #pragma unroll
            for (int jj = 0; jj < 4; jj++) {
                ulonglong2 kv = *(ulonglong2*)&sKV[(tx + jj * 32) * QS + d];
                #pragma unroll
                for (int i = 0; i < 4; i++) {
                    ffma2(acc2[i][jj], qv[i].x, kv.x);
                    ffma2(acc2[i][jj], qv[i].y, kv.y);
                }
            }
        }
        const int coff = c * CH;
        #pragma unroll
        for (int i = 0; i < 4; i++)
            #pragma unroll
            for (int jj = 0; jj < 4; jj++) {
                float2 p = unpk(acc2[i][jj]);
                sS[(tq * 4 + i) * SSTR + coff + tx + jj * 32] = (p.x + p.y) * 0.125f;
            }
    }
    __syncthreads();

    // ---- softmax (exact, band-masked); invalid entries -> 0 ----
    {
        const int warp = tid >> 5, lane = tid & 31;
        for (int m = warp; m < 64; m += 16) {
            const int qg  = q0 + m;
            const int jlo = max(lo, qg - WIN) - lo;
            const int jhi = min(hi, qg + WIN) - lo;
            float* row = sS + m * SSTR;

            float mx = -1e30f;
            for (int j = jlo + lane; j <= jhi; j += 32) mx = fmaxf(mx, row[j]);
            #pragma unroll
            for (int o = 16; o > 0; o >>= 1) mx = fmaxf(mx, __shfl_xor_sync(0xffffffffu, mx, o));

            float sum = 0.f;
            for (int j = lane; j < npad; j += 32) {
                float e = 0.f;
                if (j >= jlo && j <= jhi) e = __expf(row[j] - mx);
                row[j] = e;
                sum += e;
            }
            #pragma unroll
            for (int o = 16; o > 0; o >>= 1) sum += __shfl_xor_sync(0xffffffffu, sum, o);

            const float inv = 1.f / sum;
            for (int j = lane; j < npad; j += 32) row[j] *= inv;
        }
    }
    __syncthreads();

    // ---- dense attn write (zeros outside band) ----
    if (attnp) {
        float* base = attnp + ((size_t)((b * NHEADS + h) * SEQ + q0)) * SEQ;
        for (int f = tid; f < 64 * 512; f += 512) {
            int m = f >> 9, c4 = (f & 511) << 2;
            const float* row = sS + m * SSTR;
            float4 o;
            #pragma unroll
            for (int u = 0; u < 4; u++) {
                int cc = c4 + u;
                float v = 0.f;
                if (cc >= lo && cc <= hi) v = row[cc - lo];
                ((float*)&o)[u] = v;
            }
            *(float4*)(base + (size_t)m * SEQ + c4) = o;
        }
    }

    // ---- pass 2: AV via transposed V, split over key dim (2 groups) ----
    const int g   = tid >> 8;        // 0 or 1: which 64-key half of each chunk
    const int t   = tid & 255;
    const int ty  = t >> 4;          // q rows [ty*4, ty*4+4)
    const int txx = t & 15;          // d cols {txx + 16*dd}

    unsigned long long oacc[4][4];
    #pragma unroll
    for (int i = 0; i < 4; i++)
        #pragma unroll
        for (int dd = 0; dd < 4; dd++) oacc[i][dd] = 0ull;

    for (int c = 0; c < nch; c++) {
        const int kbase = lo + c * CH;
        __syncthreads();
        #pragma unroll
        for (int it = 0; it < 4; it++) {
            int f = tid + it * 512;          // 0..2047
            int r  = f & 127;
            int c4 = (f >> 7) << 2;
            int kr = kbase + r;
            float4 v = make_float4(0.f, 0.f, 0.f, 0.f);
            if (kr <= hi) v = *(const float4*)(g_v + ((size_t)(b * SEQ + kr)) * DMODEL + h * DK + c4);
            sKV[(c4 + 0) * VS + r] = v.x;
            sKV[(c4 + 1) * VS + r] = v.y;
            sKV[(c4 + 2) * VS + r] = v.z;
            sKV[(c4 + 3) * VS + r] = v.w;
        }
        __syncthreads();

        const int coff  = c * CH + g * 64;
        const int jloc0 = g * 64;
        #pragma unroll 4
        for (int j = 0; j < 64; j += 4) {
            ulonglong2 pv[4];
            #pragma unroll
            for (int i = 0; i < 4; i++)
                pv[i] = *(ulonglong2*)&sS[(ty * 4 + i) * SSTR + coff + j];
            #pragma unroll
            for (int dd = 0; dd < 4; dd++) {
                ulonglong2 vt = *(ulonglong2*)&sKV[(txx + 16 * dd) * VS + jloc0 + j];
                #pragma unroll
                for (int i = 0; i < 4; i++) {
                    ffma2(oacc[i][dd], pv[i].x, vt.x);
                    ffma2(oacc[i][dd], pv[i].y, vt.y);
                }
            }
        }
    }

    // horizontal finish + cross-group reduce (reuse sQ as scratch)
    float val[4][4];
    #pragma unroll
    for (int i = 0; i < 4; i++)
        #pragma unroll
        for (int dd = 0; dd < 4; dd++) {
            float2 p = unpk(oacc[i][dd]);
            val[i][dd] = p.x + p.y;
        }

    float* sRed = sQ;
    __syncthreads();
    if (g == 1) {
        #pragma unroll
        for (int i = 0; i < 4; i++)
            #pragma unroll
            for (int dd = 0; dd < 4; dd++)
                sRed[(ty * 4 + i) * QS + txx + 16 * dd] = val[i][dd];
    }
    __syncthreads();
    if (g == 0) {
        float* base = g_ctx + ((size_t)(b * SEQ + q0)) * DMODEL + h * DK;
        #pragma unroll
        for (int i = 0; i < 4; i++)
            #pragma unroll
            for (int dd = 0; dd < 4; dd++)
                base[(size_t)(ty * 4 + i) * DMODEL + txx + 16 * dd] =
                    val[i][dd] + sRed[(ty * 4 + i) * QS + txx + 16 * dd];
    }
}

// ==================== launch ====================
extern "C" void kernel_launch(void* const* d_in, const int* in_sizes, int n_in,
                              void* d_out, int out_size) {
    const float* q  = (const float*)d_in[0];
    const float* k  = (const float*)d_in[1];
    const float* v  = (const float*)d_in[2];
    const float* Wq = (const float*)d_in[3];
    const float* bq = (const float*)d_in[4];
    const float* Wk = (const float*)d_in[5];
    const float* bk = (const float*)d_in[6];
    const float* Wv = (const float*)d_in[7];
    const float* bv = (const float*)d_in[8];
    const float* Wo = (const float*)d_in[9];
    const float* bo = (const float*)d_in[10];

    float *gq, *gk, *gv, *gctx;
    cudaGetSymbolAddress((void**)&gq,   g_q);
    cudaGetSymbolAddress((void**)&gk,   g_k);
    cudaGetSymbolAddress((void**)&gv,   g_v);
    cudaGetSymbolAddress((void**)&gctx, g_ctx);

    const int ATTN_SMEM = (64 * QS + CH * QS + 64 * SSTR) * sizeof(float);  // 217088
    cudaFuncSetAttribute(attn_tile, cudaFuncAttributeMaxDynamicSharedMemorySize, ATTN_SMEM);

    QKVArgs qa;
    qa.A[0] = q;  qa.A[1] = k;  qa.A[2] = v;
    qa.W[0] = Wq; qa.W[1] = Wk; qa.W[2] = Wv;
    qa.bias[0] = bq; qa.bias[1] = bk; qa.bias[2] = bv;
    qa.C[0] = gq; qa.C[1] = gk; qa.C[2] = gv;

    dim3 ggrid(DMODEL / 128, (BATCH * SEQ) / 128, 3);   // (8, 32, 3)
    gemm_qkv<<<ggrid, 256>>>(qa);

    const size_t OUTE  = (size_t)BATCH * SEQ * DMODEL;
    const size_t ATTNE = (size_t)BATCH * NHEADS * SEQ * SEQ;
    float* outp  = (float*)d_out;
    float* attnp = ((size_t)out_size >= OUTE + ATTNE) ? (outp + OUTE) : nullptr;

    dim3 agrid(SEQ / TQ, NHEADS, BATCH);
    attn_tile<<<agrid, 512, ATTN_SMEM>>>(attnp);

    dim3 ogrid(DMODEL / 128, (BATCH * SEQ) / 128);
    gemm_single<<<ogrid, 256>>>(gctx, Wo, bo, outp);
}

// round 4
// speedup vs baseline: 3.0702x; 1.0993x over previous
#include <cuda_runtime.h>
#include <math.h>

#define BATCH  2
#define SEQ    2048
#define DMODEL 1024
#define NHEADS 16
#define DK     64
#define WIN    256

// -------- scratch (allocation-free rule: __device__ globals) --------
__device__ float g_q[BATCH * SEQ * DMODEL];
__device__ float g_k[BATCH * SEQ * DMODEL];
__device__ float g_v[BATCH * SEQ * DMODEL];
__device__ float g_ctx[BATCH * SEQ * DMODEL];

// -------- f32x2 packed-FMA helpers (Blackwell FFMA2) --------
__device__ __forceinline__ unsigned long long pack_dup(float a) {
    unsigned long long r;
    asm("mov.b64 %0, {%1, %1};" : "=l"(r) : "f"(a));
    return r;
}
__device__ __forceinline__ void ffma2(unsigned long long& d,
                                      unsigned long long a,
                                      unsigned long long b) {
    asm("fma.rn.f32x2 %0, %1, %2, %0;" : "+l"(d) : "l"(a), "l"(b));
}
__device__ __forceinline__ float2 unpk(unsigned long long v) {
    float2 f;
    asm("mov.b64 {%0, %1}, %2;" : "=f"(f.x), "=f"(f.y) : "l"(v));
    return f;
}

// ==================== GEMM: C = A @ W + bias (f32x2 inner) ====================
// 128x128 tile, BK=16, 256 threads, 8x8 per thread, double-buffered smem.
// Warp output footprint = 64(M) x 32(N): wy=lane>>2 (8), wx=lane&3 (4)
//   -> B smem loads conflict-free (4 distinct @ bank stride 8), A 2-way.
struct QKVArgs {
    const float* A[3];
    const float* W[3];
    const float* bias[3];
    float*       C[3];
};

__device__ __forceinline__
void gemm_body(const float* __restrict__ A, const float* __restrict__ W,
               const float* __restrict__ bias, float* __restrict__ C,
               float As[2][16][128], float Bs[2][16][128]) {
    const int K = DMODEL, N = DMODEL;
    const int tid  = threadIdx.x;
    const int brow = blockIdx.y << 7;
    const int bcol = blockIdx.x << 7;

    const int lane = tid & 31, wid = tid >> 5;
    const int tr = ((wid >> 2) << 3) + (lane >> 2);   // 0..15
    const int tc = ((wid & 3) << 2) + (lane & 3);     // 0..15

    const int ar0  = tid >> 2;
    const int ar1  = ar0 + 64;
    const int akc  = (tid & 3) << 2;
    const int bk0  = tid >> 5;
    const int bk1  = bk0 + 8;
    const int bnc  = (tid & 31) << 2;

    float4 a0v, a1v, b0v, b1v;

    a0v = *(const float4*)(A + (size_t)(brow + ar0) * K + akc);
    a1v = *(const float4*)(A + (size_t)(brow + ar1) * K + akc);
    b0v = *(const float4*)(W + (size_t)bk0 * N + bcol + bnc);
    b1v = *(const float4*)(W + (size_t)bk1 * N + bcol + bnc);
    As[0][akc + 0][ar0] = a0v.x; As[0][akc + 1][ar0] = a0v.y;
    As[0][akc + 2][ar0] = a0v.z; As[0][akc + 3][ar0] = a0v.w;
    As[0][akc + 0][ar1] = a1v.x; As[0][akc + 1][ar1] = a1v.y;
    As[0][akc + 2][ar1] = a1v.z; As[0][akc + 3][ar1] = a1v.w;
    *(float4*)&Bs[0][bk0][bnc] = b0v;
    *(float4*)&Bs[0][bk1][bnc] = b1v;
    __syncthreads();

    unsigned long long acc2[8][4];
    #pragma unroll
    for (int i = 0; i < 8; i++)
        #pragma unroll
        for (int j = 0; j < 4; j++) acc2[i][j] = 0ull;

    const int nt = K >> 4;
    for (int kt = 0; kt < nt; kt++) {
        const int cur = kt & 1;
        if (kt + 1 < nt) {
            const int k0 = (kt + 1) << 4;
            a0v = *(const float4*)(A + (size_t)(brow + ar0) * K + k0 + akc);
            a1v = *(const float4*)(A + (size_t)(brow + ar1) * K + k0 + akc);
            b0v = *(const float4*)(W + (size_t)(k0 + bk0) * N + bcol + bnc);
            b1v = *(const float4*)(W + (size_t)(k0 + bk1) * N + bcol + bnc);
        }
        #pragma unroll
        for (int kk = 0; kk < 16; kk++) {
            float4 x0 = *(float4*)&As[cur][kk][tr * 8];
            float4 x1 = *(float4*)&As[cur][kk][tr * 8 + 4];
            ulonglong2 y0 = *(ulonglong2*)&Bs[cur][kk][tc * 8];
            ulonglong2 y1 = *(ulonglong2*)&Bs[cur][kk][tc * 8 + 4];
            float a[8] = {x0.x, x0.y, x0.z, x0.w, x1.x, x1.y, x1.z, x1.w};
            #pragma unroll
            for (int i = 0; i < 8; i++) {
                unsigned long long ad = pack_dup(a[i]);
                ffma2(acc2[i][0], ad, y0.x);
                ffma2(acc2[i][1], ad, y0.y);
                ffma2(acc2[i][2], ad, y1.x);
                ffma2(acc2[i][3], ad, y1.y);
            }
        }
        if (kt + 1 < nt) {
            const int nxt = cur ^ 1;
            As[nxt][akc + 0][ar0] = a0v.x; As[nxt][akc + 1][ar0] = a0v.y;
            As[nxt][akc + 2][ar0] = a0v.z; As[nxt][akc + 3][ar0] = a0v.w;
            As[nxt][akc + 0][ar1] = a1v.x; As[nxt][akc + 1][ar1] = a1v.y;
            As[nxt][akc + 2][ar1] = a1v.z; As[nxt][akc + 3][ar1] = a1v.w;
            *(float4*)&Bs[nxt][bk0][bnc] = b0v;
            *(float4*)&Bs[nxt][bk1][bnc] = b1v;
        }
        __syncthreads();
    }

    float4 bb0 = *(const float4*)(bias + bcol + tc * 8);
    float4 bb1 = *(const float4*)(bias + bcol + tc * 8 + 4);
    #pragma unroll
    for (int i = 0; i < 8; i++) {
        const int row = brow + tr * 8 + i;
        const int col = bcol + tc * 8;
        float2 p0 = unpk(acc2[i][0]);
        float2 p1 = unpk(acc2[i][1]);
        float2 p2 = unpk(acc2[i][2]);
        float2 p3 = unpk(acc2[i][3]);
        float4 o0 = make_float4(p0.x + bb0.x, p0.y + bb0.y, p1.x + bb0.z, p1.y + bb0.w);
        float4 o1 = make_float4(p2.x + bb1.x, p2.y + bb1.y, p3.x + bb1.z, p3.y + bb1.w);
        *(float4*)(C + (size_t)row * DMODEL + col)     = o0;
        *(float4*)(C + (size_t)row * DMODEL + col + 4) = o1;
    }
}

__global__ __launch_bounds__(256, 2)
void gemm_qkv(QKVArgs args) {
    __shared__ float As[2][16][128];
    __shared__ float Bs[2][16][128];
    const int z = blockIdx.z;
    gemm_body(args.A[z], args.W[z], args.bias[z], args.C[z], As, Bs);
}

__global__ __launch_bounds__(256, 2)
void gemm_single(const float* __restrict__ A, const float* __restrict__ W,
                 const float* __restrict__ bias, float* __restrict__ C) {
    __shared__ float As[2][16][128];
    __shared__ float Bs[2][16][128];
    gemm_body(A, W, bias, C, As, Bs);
}

// ==================== Tiled sliding-window attention ====================
// 512 threads per block, 64 queries per block, 128-key chunks.
#define TQ   64
#define CH   128
#define QS   68     // sQ row stride
#define VS   132    // sVT row stride (d-major V transpose)
#define SSTR 644    // sS row stride (>= 5*128, 16B-aligned rows)

__global__ __launch_bounds__(512)
void attn_tile(float* __restrict__ attnp) {
    extern __shared__ float sm[];
    float* sQ  = sm;                 // 64 x 68   = 4352 floats
    float* sKV = sQ + 64 * QS;       // 8704 floats (K: 128x68 / VT: 64x132)
    float* sS  = sKV + CH * QS;      // 64 x 644

    const int qt = blockIdx.x, h = blockIdx.y, b = blockIdx.z;
    const int q0 = qt * TQ;
    const int tid = threadIdx.x;

    const int lo   = max(0, q0 - WIN);
    const int hi   = min(SEQ - 1, q0 + TQ - 1 + WIN);
    const int cnt  = hi - lo + 1;               // <= 576
    const int nch  = (cnt + CH - 1) / CH;       // <= 5
    const int npad = nch * CH;

    // ---- load Q tile ----
    {
        const float* base = g_q + ((size_t)(b * SEQ + q0)) * DMODEL + h * DK;
        #pragma unroll
        for (int it = 0; it < 2; it++) {
            int f = tid + it * 512;
            int r = f >> 4, c4 = (f & 15) << 2;
            *(float4*)&sQ[r * QS + c4] = *(const float4*)(base + (size_t)r * DMODEL + c4);
        }
    }

    // ---- pass 1: scores (f32x2 packed over d) ----
    // warp footprint: 4 q-threads x 8 k-threads -> conflict-free K loads
    const int lane = tid & 31, wrp = tid >> 5;
    const int tq = ((wrp >> 2) << 2) + ((lane >> 3) & 3);  // 0..15
    const int tx = ((wrp & 3) << 3) + (lane & 7);          // 0..31
    for (int c = 0; c < nch; c++) {
        const int kbase = lo + c * CH;
        __syncthreads();
        #pragma unroll
        for (int it = 0; it < 4; it++) {
            int f = tid + it * 512;
            int r = f >> 4, c4 = (f & 15) << 2;
            int kr = kbase + r;
            float4 v = make_float4(0.f, 0.f, 0.f, 0.f);
            if (kr <= hi) v = *(const float4*)(g_k + ((size_t)(b * SEQ + kr)) * DMODEL + h * DK + c4);
            *(float4*)&sKV[r * QS + c4] = v;
        }
        __syncthreads();

        unsigned long long acc2[4][4];
        #pragma unroll
        for (int i = 0; i < 4; i++)
            #pragma unroll
            for (int j = 0; j < 4; j++) acc2[i][j] = 0ull;

        #pragma unroll
        for (int d = 0; d < 64; d += 4) {
            ulonglong2 qv[4];
            #pragma unroll
            for (int i = 0; i < 4; i++)
                qv[i] = *(ulonglong2*)&sQ[(tq * 4 + i) * QS + d];
            #pragma unroll
            for (int jj = 0; jj < 4; jj++) {
                ulonglong2 kv = *(ulonglong2*)&sKV[(tx + jj * 32) * QS + d];
                #pragma unroll
                for (int i = 0; i < 4; i++) {
                    ffma2(acc2[i][jj], qv[i].x, kv.x);
                    ffma2(acc2[i][jj], qv[i].y, kv.y);
                }
            }
        }
        const int coff = c * CH;
        #pragma unroll
        for (int i = 0; i < 4; i++)
            #pragma unroll
            for (int jj = 0; jj < 4; jj++) {
                float2 p = unpk(acc2[i][jj]);
                sS[(tq * 4 + i) * SSTR + coff + tx + jj * 32] = (p.x + p.y) * 0.125f;
            }
    }
    __syncthreads();

    // ---- softmax (exact, band-masked); invalid entries -> 0 ----
    {
        const int warp = tid >> 5, ln = tid & 31;
        for (int m = warp; m < 64; m += 16) {
            const int qg  = q0 + m;
            const int jlo = max(lo, qg - WIN) - lo;
            const int jhi = min(hi, qg + WIN) - lo;
            float* row = sS + m * SSTR;

            float mx = -1e30f;
            for (int j = jlo + ln; j <= jhi; j += 32) mx = fmaxf(mx, row[j]);
            #pragma unroll
            for (int o = 16; o > 0; o >>= 1) mx = fmaxf(mx, __shfl_xor_sync(0xffffffffu, mx, o));

            float sum = 0.f;
            for (int j = ln; j < npad; j += 32) {
                float e = 0.f;
                if (j >= jlo && j <= jhi) e = __expf(row[j] - mx);
                row[j] = e;
                sum += e;
            }
            #pragma unroll
            for (int o = 16; o > 0; o >>= 1) sum += __shfl_xor_sync(0xffffffffu, sum, o);

            const float inv = 1.f / sum;
            for (int j = ln; j < npad; j += 32) row[j] *= inv;
        }
    }
    __syncthreads();

    // ---- dense attn write (zeros outside band) ----
    if (attnp) {
        float* base = attnp + ((size_t)((b * NHEADS + h) * SEQ + q0)) * SEQ;
        for (int f = tid; f < 64 * 512; f += 512) {
            int m = f >> 9, c4 = (f & 511) << 2;
            const float* row = sS + m * SSTR;
            float4 o;
            #pragma unroll
            for (int u = 0; u < 4; u++) {
                int cc = c4 + u;
                float v = 0.f;
                if (cc >= lo && cc <= hi) v = row[cc - lo];
                ((float*)&o)[u] = v;
            }
            *(float4*)(base + (size_t)m * SEQ + c4) = o;
        }
    }

    // ---- pass 2: AV via transposed V, split over key dim (2 groups) ----
    // per-group warp footprint: 4 q-threads x 8 d-threads -> conflict-free V reads
    const int g   = tid >> 8;        // 0 or 1: which 64-key half of each chunk
    const int t   = tid & 255;
    const int w8  = t >> 5;          // 0..7
    const int ln8 = t & 31;
    const int ty  = ((w8 >> 1) << 2) + ((ln8 >> 3) & 3);  // 0..15
    const int txx = ((w8 & 1) << 3) + (ln8 & 7);          // 0..15

    unsigned long long oacc[4][4];
    #pragma unroll
    for (int i = 0; i < 4; i++)
        #pragma unroll
        for (int dd = 0; dd < 4; dd++) oacc[i][dd] = 0ull;

    for (int c = 0; c < nch; c++) {
        const int kbase = lo + c * CH;
        __syncthreads();
        #pragma unroll
        for (int it = 0; it < 4; it++) {
            int f = tid + it * 512;          // 0..2047
            int r  = f & 127;
            int c4 = (f >> 7) << 2;
            int kr = kbase + r;
            float4 v = make_float4(0.f, 0.f, 0.f, 0.f);
            if (kr <= hi) v = *(const float4*)(g_v + ((size_t)(b * SEQ + kr)) * DMODEL + h * DK + c4);
            sKV[(c4 + 0) * VS + r] = v.x;
            sKV[(c4 + 1) * VS + r] = v.y;
            sKV[(c4 + 2) * VS + r] = v.z;
            sKV[(c4 + 3) * VS + r] = v.w;
        }
        __syncthreads();

        const int coff  = c * CH + g * 64;
        const int jloc0 = g * 64;
        #pragma unroll 4
        for (int j = 0; j < 64; j += 4) {
            ulonglong2 pv[4];
            #pragma unroll
            for (int i = 0; i < 4; i++)
                pv[i] = *(ulonglong2*)&sS[(ty * 4 + i) * SSTR + coff + j];
            #pragma unroll
            for (int dd = 0; dd < 4; dd++) {
                ulonglong2 vt = *(ulonglong2*)&sKV[(txx + 16 * dd) * VS + jloc0 + j];
                #pragma unroll
                for (int i = 0; i < 4; i++) {
                    ffma2(oacc[i][dd], pv[i].x, vt.x);
                    ffma2(oacc[i][dd], pv[i].y, vt.y);
                }
            }
        }
    }

    // horizontal finish + cross-group reduce (reuse sQ as scratch)
    float val[4][4];
    #pragma unroll
    for (int i = 0; i < 4; i++)
        #pragma unroll
        for (int dd = 0; dd < 4; dd++) {
            float2 p = unpk(oacc[i][dd]);
            val[i][dd] = p.x + p.y;
        }

    float* sRed = sQ;
    __syncthreads();
    if (g == 1) {
        #pragma unroll
        for (int i = 0; i < 4; i++)
            #pragma unroll
            for (int dd = 0; dd < 4; dd++)
                sRed[(ty * 4 + i) * QS + txx + 16 * dd] = val[i][dd];
    }
    __syncthreads();
    if (g == 0) {
        float* base = g_ctx + ((size_t)(b * SEQ + q0)) * DMODEL + h * DK;
        #pragma unroll
        for (int i = 0; i < 4; i++)
            #pragma unroll
            for (int dd = 0; dd < 4; dd++)
                base[(size_t)(ty * 4 + i) * DMODEL + txx + 16 * dd] =
                    val[i][dd] + sRed[(ty * 4 + i) * QS + txx + 16 * dd];
    }
}

// ==================== launch ====================
extern "C" void kernel_launch(void* const* d_in, const int* in_sizes, int n_in,
                              void* d_out, int out_size) {
    const float* q  = (const float*)d_in[0];
    const float* k  = (const float*)d_in[1];
    const float* v  = (const float*)d_in[2];
    const float* Wq = (const float*)d_in[3];
    const float* bq = (const float*)d_in[4];
    const float* Wk = (const float*)d_in[5];
    const float* bk = (const float*)d_in[6];
    const float* Wv = (const float*)d_in[7];
    const float* bv = (const float*)d_in[8];
    const float* Wo = (const float*)d_in[9];
    const float* bo = (const float*)d_in[10];

    float *gq, *gk, *gv, *gctx;
    cudaGetSymbolAddress((void**)&gq,   g_q);
    cudaGetSymbolAddress((void**)&gk,   g_k);
    cudaGetSymbolAddress((void**)&gv,   g_v);
    cudaGetSymbolAddress((void**)&gctx, g_ctx);

    const int ATTN_SMEM = (64 * QS + CH * QS + 64 * SSTR) * sizeof(float);  // 217088
    cudaFuncSetAttribute(attn_tile, cudaFuncAttributeMaxDynamicSharedMemorySize, ATTN_SMEM);

    QKVArgs qa;
    qa.A[0] = q;  qa.A[1] = k;  qa.A[2] = v;
    qa.W[0] = Wq; qa.W[1] = Wk; qa.W[2] = Wv;
    qa.bias[0] = bq; qa.bias[1] = bk; qa.bias[2] = bv;
    qa.C[0] = gq; qa.C[1] = gk; qa.C[2] = gv;

    dim3 ggrid(DMODEL / 128, (BATCH * SEQ) / 128, 3);   // (8, 32, 3)
    gemm_qkv<<<ggrid, 256>>>(qa);

    const size_t OUTE  = (size_t)BATCH * SEQ * DMODEL;
    const size_t ATTNE = (size_t)BATCH * NHEADS * SEQ * SEQ;
    float* outp  = (float*)d_out;
    float* attnp = ((size_t)out_size >= OUTE + ATTNE) ? (outp + OUTE) : nullptr;

    dim3 agrid(SEQ / TQ, NHEADS, BATCH);
    attn_tile<<<agrid, 512, ATTN_SMEM>>>(attnp);

    dim3 ogrid(DMODEL / 128, (BATCH * SEQ) / 128);
    gemm_single<<<ogrid, 256>>>(gctx, Wo, bo, outp);
}

// round 6
// speedup vs baseline: 4.2673x; 1.3899x over previous
#include <cuda_runtime.h>
#include <cuda_bf16.h>
#include <math.h>
#include <stdint.h>

#define BATCH  2
#define SEQ    2048
#define DMODEL 1024
#define NHEADS 16
#define DK     64
#define WIN    256

// -------- scratch (allocation-free rule: __device__ globals) --------
__device__ float g_q[BATCH * SEQ * DMODEL];
__device__ float g_k[BATCH * SEQ * DMODEL];
__device__ float g_v[BATCH * SEQ * DMODEL];
__device__ float g_ctx[BATCH * SEQ * DMODEL];
// transposed+split weights: [4][N=1024][K=1024] bf16
__device__ __nv_bfloat16 g_wt_hi[4 * DMODEL * DMODEL];
__device__ __nv_bfloat16 g_wt_lo[4 * DMODEL * DMODEL];

// -------- f32x2 packed-FMA helpers (attention kernel) --------
__device__ __forceinline__ void ffma2(unsigned long long& d,
                                      unsigned long long a,
                                      unsigned long long b) {
    asm("fma.rn.f32x2 %0, %1, %2, %0;" : "+l"(d) : "l"(a), "l"(b));
}
__device__ __forceinline__ float2 unpk(unsigned long long v) {
    float2 f;
    asm("mov.b64 {%0, %1}, %2;" : "=f"(f.x), "=f"(f.y) : "l"(v));
    return f;
}

// -------- baseline tensor-core helpers (sm_80+ PTX, safe on sm_103) --------
__device__ __forceinline__ uint32_t s2u(const void* p) {
    uint32_t a;
    asm("{ .reg .u64 t; cvta.to.shared.u64 t, %1; cvt.u32.u64 %0, t; }"
        : "=r"(a) : "l"(p));
    return a;
}
__device__ __forceinline__ void ldmx4(uint32_t* r, uint32_t addr) {
    asm volatile("ldmatrix.sync.aligned.m8n8.x4.shared.b16 {%0,%1,%2,%3}, [%4];"
                 : "=r"(r[0]), "=r"(r[1]), "=r"(r[2]), "=r"(r[3]) : "r"(addr));
}
__device__ __forceinline__ void ldmx2(uint32_t* r, uint32_t addr) {
    asm volatile("ldmatrix.sync.aligned.m8n8.x2.shared.b16 {%0,%1}, [%2];"
                 : "=r"(r[0]), "=r"(r[1]) : "r"(addr));
}
__device__ __forceinline__ void mma_bf16(float* c, const uint32_t* a, const uint32_t* b) {
    asm volatile(
        "mma.sync.aligned.m16n8k16.row.col.f32.bf16.bf16.f32 "
        "{%0,%1,%2,%3}, {%4,%5,%6,%7}, {%8,%9}, {%0,%1,%2,%3};"
        : "+f"(c[0]), "+f"(c[1]), "+f"(c[2]), "+f"(c[3])
        : "r"(a[0]), "r"(a[1]), "r"(a[2]), "r"(a[3]), "r"(b[0]), "r"(b[1]));
}
#define CP_ASYNC16(dst, src) \
    asm volatile("cp.async.ca.shared.global [%0], [%1], 16;" :: "r"(dst), "l"(src))
#define CP_COMMIT()  asm volatile("cp.async.commit_group;" ::: "memory")
#define CP_WAIT0()   asm volatile("cp.async.wait_group 0;" ::: "memory")

__device__ __forceinline__ uint32_t hi_pack(float a, float b) {
    return __byte_perm(__float_as_uint(a), __float_as_uint(b), 0x7632);
}
__device__ __forceinline__ uint32_t lo_pack(float a, float b) {
    float ra = a - __uint_as_float(__float_as_uint(a) & 0xffff0000u);
    float rb = b - __uint_as_float(__float_as_uint(b) & 0xffff0000u);
    __nv_bfloat162 p = __floats2bfloat162_rn(ra, rb);
    return *(uint32_t*)&p;
}

// ==================== weight prep: Wt[n,k] = W[k,n], split hi/lo bf16 ====================
struct WPrep { const float* w[4]; };

__global__ __launch_bounds__(256)
void prep_w(WPrep wp, __nv_bfloat16* __restrict__ hi, __nv_bfloat16* __restrict__ lo) {
    __shared__ float t[32][33];
    const int wi = blockIdx.z;
    const float* W = wp.w[wi];
    const int n0 = blockIdx.x * 32, k0 = blockIdx.y * 32;
    const int tx = threadIdx.x & 31, ty = (threadIdx.x >> 5) * 4;
    #pragma unroll
    for (int i = 0; i < 4; i++)
        t[ty + i][tx] = W[(size_t)(k0 + ty + i) * DMODEL + n0 + tx];
    __syncthreads();
    #pragma unroll
    for (int i = 0; i < 4; i++) {
        float a = t[tx][ty + i];
        __nv_bfloat16 h = __float2bfloat16_rz(a);
        float hf = __bfloat162float(h);
        __nv_bfloat16 l = __float2bfloat16(a - hf);
        size_t idx = (size_t)wi * DMODEL * DMODEL + (size_t)(n0 + ty + i) * DMODEL + k0 + tx;
        hi[idx] = h;
        lo[idx] = l;
    }
}

// ==================== HMMA split-bf16 GEMM: C = A @ W + bias ====================
// 128x128x32 CTA tile, 8 warps (2x4), warp tile 64x32, double-buffered smem.
// smem layout per stage (32KB): A[128 rows][128B: hi(4x16B) | lo(4x16B)], then B same.
struct GemmJob {
    const float* A[3];
    const __nv_bfloat16* Bh[3];
    const __nv_bfloat16* Bl[3];
    const float* bias[3];
    float* C[3];
};

__device__ __forceinline__
void gemm_mma_body(const float* __restrict__ A, const __nv_bfloat16* __restrict__ Bh,
                   const __nv_bfloat16* __restrict__ Bl, const float* __restrict__ bias,
                   float* __restrict__ C) {
    extern __shared__ char smx[];
    const int tid = threadIdx.x, lane = tid & 31, wid = tid >> 5;
    const int brow = blockIdx.y << 7, bcol = blockIdx.x << 7;
    const int wm = (wid >> 2) << 6;   // 0 or 64
    const int wn = (wid & 3) << 5;    // 0,32,64,96

    const uint32_t sbase = s2u(smx);

    float acc[4][4][4];
    #pragma unroll
    for (int i = 0; i < 4; i++)
        #pragma unroll
        for (int j = 0; j < 4; j++)
            #pragma unroll
            for (int u = 0; u < 4; u++) acc[i][j][u] = 0.f;

    // ---- prologue: chunk 0 into stage 0 ----
    {
        #pragma unroll
        for (int it = 0; it < 2; it++) {
            int f = tid + it * 256;
            int row = f >> 2, grp = f & 3;
            const __nv_bfloat16* srcH = Bh + (size_t)(bcol + row) * DMODEL + grp * 8;
            const __nv_bfloat16* srcL = Bl + (size_t)(bcol + row) * DMODEL + grp * 8;
            uint32_t dH = sbase + 16384u + row * 128 + ((grp ^ (row & 7)) << 4);
            uint32_t dL = sbase + 16384u + row * 128 + (((grp + 4) ^ (row & 7)) << 4);
            CP_ASYNC16(dH, srcH);
            CP_ASYNC16(dL, srcL);
        }
        CP_COMMIT();
        #pragma unroll
        for (int it = 0; it < 2; it++) {
            int f = tid + it * 256;
            int row = f >> 2, grp = f & 3;
            const float* ap = A + (size_t)(brow + row) * DMODEL + grp * 8;
            float4 f0 = *(const float4*)ap, f1 = *(const float4*)(ap + 4);
            uint4 ah = make_uint4(hi_pack(f0.x, f0.y), hi_pack(f0.z, f0.w),
                                  hi_pack(f1.x, f1.y), hi_pack(f1.z, f1.w));
            uint4 al = make_uint4(lo_pack(f0.x, f0.y), lo_pack(f0.z, f0.w),
                                  lo_pack(f1.x, f1.y), lo_pack(f1.z, f1.w));
            *(uint4*)(smx + row * 128 + ((grp ^ (row & 7)) << 4)) = ah;
            *(uint4*)(smx + row * 128 + (((grp + 4) ^ (row & 7)) << 4)) = al;
        }
        CP_WAIT0();
        __syncthreads();
    }

    for (int kt = 0; kt < 32; kt++) {
        const int s = kt & 1;
        const uint32_t soff = (uint32_t)s << 15;

        float4 pf[2][2];
        if (kt < 31) {
            const int k0 = (kt + 1) << 5;
            const uint32_t noff = (uint32_t)(s ^ 1) << 15;
            #pragma unroll
            for (int it = 0; it < 2; it++) {
                int f = tid + it * 256;
                int row = f >> 2, grp = f & 3;
                const __nv_bfloat16* srcH = Bh + (size_t)(bcol + row) * DMODEL + k0 + grp * 8;
                const __nv_bfloat16* srcL = Bl + (size_t)(bcol + row) * DMODEL + k0 + grp * 8;
                uint32_t dH = sbase + noff + 16384u + row * 128 + ((grp ^ (row & 7)) << 4);
                uint32_t dL = sbase + noff + 16384u + row * 128 + (((grp + 4) ^ (row & 7)) << 4);
                CP_ASYNC16(dH, srcH);
                CP_ASYNC16(dL, srcL);
                const float* ap = A + (size_t)(brow + row) * DMODEL + k0 + grp * 8;
                pf[it][0] = *(const float4*)ap;
                pf[it][1] = *(const float4*)(ap + 4);
            }
            CP_COMMIT();
        }

        // ---- compute current stage: 2 k16 steps ----
        const uint32_t aBase = sbase + soff;
        const uint32_t bBase = sbase + soff + 16384u;
        #pragma unroll
        for (int ks2 = 0; ks2 < 2; ks2++) {
            uint32_t aH[4][4], aL[4][4], bH[4][2], bL[4][2];
            const int cA = (ks2 << 1) + (lane >> 4);
            #pragma unroll
            for (int i = 0; i < 4; i++) {
                int r = wm + i * 16 + (lane & 15);
                ldmx4(aH[i], aBase + r * 128 + ((cA ^ (r & 7)) << 4));
                ldmx4(aL[i], aBase + r * 128 + (((cA + 4) ^ (r & 7)) << 4));
            }
            const int cB = (ks2 << 1) + ((lane >> 3) & 1);
            #pragma unroll
            for (int j = 0; j < 4; j++) {
                int rn = wn + j * 8 + (lane & 7);
                ldmx2(bH[j], bBase + rn * 128 + ((cB ^ (rn & 7)) << 4));
                ldmx2(bL[j], bBase + rn * 128 + (((cB + 4) ^ (rn & 7)) << 4));
            }
            #pragma unroll
            for (int i = 0; i < 4; i++)
                #pragma unroll
                for (int j = 0; j < 4; j++) {
                    mma_bf16(acc[i][j], aH[i], bH[j]);
                    mma_bf16(acc[i][j], aH[i], bL[j]);
                    mma_bf16(acc[i][j], aL[i], bH[j]);
                }
        }

        if (kt < 31) {
            const uint32_t noff = (uint32_t)(s ^ 1) << 15;
            #pragma unroll
            for (int it = 0; it < 2; it++) {
                int f = tid + it * 256;
                int row = f >> 2, grp = f & 3;
                float4 f0 = pf[it][0], f1 = pf[it][1];
                uint4 ah = make_uint4(hi_pack(f0.x, f0.y), hi_pack(f0.z, f0.w),
                                      hi_pack(f1.x, f1.y), hi_pack(f1.z, f1.w));
                uint4 al = make_uint4(lo_pack(f0.x, f0.y), lo_pack(f0.z, f0.w),
                                      lo_pack(f1.x, f1.y), lo_pack(f1.z, f1.w));
                *(uint4*)(smx + noff + row * 128 + ((grp ^ (row & 7)) << 4)) = ah;
                *(uint4*)(smx + noff + row * 128 + (((grp + 4) ^ (row & 7)) << 4)) = al;
            }
            CP_WAIT0();
        }
        __syncthreads();
    }

    // ---- epilogue: write C with bias ----
    const int g = lane >> 2, tg = lane & 3;
    #pragma unroll
    for (int i = 0; i < 4; i++) {
        const int r0 = brow + wm + i * 16 + g;
        #pragma unroll
        for (int j = 0; j < 4; j++) {
            const int col = bcol + wn + j * 8 + tg * 2;
            float2 bb = *(const float2*)(bias + col);
            float2 o0 = make_float2(acc[i][j][0] + bb.x, acc[i][j][1] + bb.y);
            float2 o1 = make_float2(acc[i][j][2] + bb.x, acc[i][j][3] + bb.y);
            *(float2*)(C + (size_t)r0 * DMODEL + col)       = o0;
            *(float2*)(C + (size_t)(r0 + 8) * DMODEL + col) = o1;
        }
    }
}

__global__ __launch_bounds__(256)
void gemm_mma_qkv(GemmJob job) {
    const int z = blockIdx.z;
    gemm_mma_body(job.A[z], job.Bh[z], job.Bl[z], job.bias[z], job.C[z]);
}

__global__ __launch_bounds__(256)
void gemm_mma_one(const float* __restrict__ A, const __nv_bfloat16* __restrict__ Bh,
                  const __nv_bfloat16* __restrict__ Bl, const float* __restrict__ bias,
                  float* __restrict__ C) {
    gemm_mma_body(A, Bh, Bl, bias, C);
}

// ==================== Tiled sliding-window attention (unchanged) ====================
#define TQ   64
#define CH   128
#define QS   68
#define VS   132
#define SSTR 644

__global__ __launch_bounds__(512)
void attn_tile(float* __restrict__ attnp) {
    extern __shared__ float sm[];
    float* sQ  = sm;
    float* sKV = sQ + 64 * QS;
    float* sS  = sKV + CH * QS;

    const int qt = blockIdx.x, h = blockIdx.y, b = blockIdx.z;
    const int q0 = qt * TQ;
    const int tid = threadIdx.x;

    const int lo   = max(0, q0 - WIN);
    const int hi   = min(SEQ - 1, q0 + TQ - 1 + WIN);
    const int cnt  = hi - lo + 1;
    const int nch  = (cnt + CH - 1) / CH;
    const int npad = nch * CH;

    {
        const float* base = g_q + ((size_t)(b * SEQ + q0)) * DMODEL + h * DK;
        #pragma unroll
        for (int it = 0; it < 2; it++) {
            int f = tid + it * 512;
            int r = f >> 4, c4 = (f & 15) << 2;
            *(float4*)&sQ[r * QS + c4] = *(const float4*)(base + (size_t)r * DMODEL + c4);
        }
    }

    const int lane = tid & 31, wrp = tid >> 5;
    const int tq = ((wrp >> 2) << 2) + ((lane >> 3) & 3);
    const int tx = ((wrp & 3) << 3) + (lane & 7);
    for (int c = 0; c < nch; c++) {
        const int kbase = lo + c * CH;
        __syncthreads();
        #pragma unroll
        for (int it = 0; it < 4; it++) {
            int f = tid + it * 512;
            int r = f >> 4, c4 = (f & 15) << 2;
            int kr = kbase + r;
            float4 v = make_float4(0.f, 0.f, 0.f, 0.f);
            if (kr <= hi) v = *(const float4*)(g_k + ((size_t)(b * SEQ + kr)) * DMODEL + h * DK + c4);
            *(float4*)&sKV[r * QS + c4] = v;
        }
        __syncthreads();

        unsigned long long acc2[4][4];
        #pragma unroll
        for (int i = 0; i < 4; i++)
            #pragma unroll
            for (int j = 0; j < 4; j++) acc2[i][j] = 0ull;

        #pragma unroll
        for (int d = 0; d < 64; d += 4) {
            ulonglong2 qv[4];
            #pragma unroll
            for (int i = 0; i < 4; i++)
                qv[i] = *(ulonglong2*)&sQ[(tq * 4 + i) * QS + d];
            #pragma unroll
            for (int jj = 0; jj < 4; jj++) {
                ulonglong2 kv = *(ulonglong2*)&sKV[(tx + jj * 32) * QS + d];
                #pragma unroll
                for (int i = 0; i < 4; i++) {
                    ffma2(acc2[i][jj], qv[i].x, kv.x);
                    ffma2(acc2[i][jj], qv[i].y, kv.y);
                }
            }
        }
        const int coff = c * CH;
        #pragma unroll
        for (int i = 0; i < 4; i++)
            #pragma unroll
            for (int jj = 0; jj < 4; jj++) {
                float2 p = unpk(acc2[i][jj]);
                sS[(tq * 4 + i) * SSTR + coff + tx + jj * 32] = (p.x + p.y) * 0.125f;
            }
    }
    __syncthreads();

    {
        const int warp = tid >> 5, ln = tid & 31;
        for (int m = warp; m < 64; m += 16) {
            const int qg  = q0 + m;
            const int jlo = max(lo, qg - WIN) - lo;
            const int jhi = min(hi, qg + WIN) - lo;
            float* row = sS + m * SSTR;

            float mx = -1e30f;
            for (int j = jlo + ln; j <= jhi; j += 32) mx = fmaxf(mx, row[j]);
            #pragma unroll
            for (int o = 16; o > 0; o >>= 1) mx = fmaxf(mx, __shfl_xor_sync(0xffffffffu, mx, o));

            float sum = 0.f;
            for (int j = ln; j < npad; j += 32) {
                float e = 0.f;
                if (j >= jlo && j <= jhi) e = __expf(row[j] - mx);
                row[j] = e;
                sum += e;
            }
            #pragma unroll
            for (int o = 16; o > 0; o >>= 1) sum += __shfl_xor_sync(0xffffffffu, sum, o);

            const float inv = 1.f / sum;
            for (int j = ln; j < npad; j += 32) row[j] *= inv;
        }
    }
    __syncthreads();

    if (attnp) {
        float* base = attnp + ((size_t)((b * NHEADS + h) * SEQ + q0)) * SEQ;
        for (int f = tid; f < 64 * 512; f += 512) {
            int m = f >> 9, c4 = (f & 511) << 2;
            const float* row = sS + m * SSTR;
            float4 o;
            #pragma unroll
            for (int u = 0; u < 4; u++) {
                int cc = c4 + u;
                float v = 0.f;
                if (cc >= lo && cc <= hi) v = row[cc - lo];
                ((float*)&o)[u] = v;
            }
            *(float4*)(base + (size_t)m * SEQ + c4) = o;
        }
    }

    const int g   = tid >> 8;
    const int t   = tid & 255;
    const int w8  = t >> 5;
    const int ln8 = t & 31;
    const int ty  = ((w8 >> 1) << 2) + ((ln8 >> 3) & 3);
    const int txx = ((w8 & 1) << 3) + (ln8 & 7);

    unsigned long long oacc[4][4];
    #pragma unroll
    for (int i = 0; i < 4; i++)
        #pragma unroll
        for (int dd = 0; dd < 4; dd++) oacc[i][dd] = 0ull;

    for (int c = 0; c < nch; c++) {
        const int kbase = lo + c * CH;
        __syncthreads();
        #pragma unroll
        for (int it = 0; it < 4; it++) {
            int f = tid + it * 512;
            int r  = f & 127;
            int c4 = (f >> 7) << 2;
            int kr = kbase + r;
            float4 v = make_float4(0.f, 0.f, 0.f, 0.f);
            if (kr <= hi) v = *(const float4*)(g_v + ((size_t)(b * SEQ + kr)) * DMODEL + h * DK + c4);
            sKV[(c4 + 0) * VS + r] = v.x;
            sKV[(c4 + 1) * VS + r] = v.y;
            sKV[(c4 + 2) * VS + r] = v.z;
            sKV[(c4 + 3) * VS + r] = v.w;
        }
        __syncthreads();

        const int coff  = c * CH + g * 64;
        const int jloc0 = g * 64;
        #pragma unroll 4
        for (int j = 0; j < 64; j += 4) {
            ulonglong2 pv[4];
            #pragma unroll
            for (int i = 0; i < 4; i++)
                pv[i] = *(ulonglong2*)&sS[(ty * 4 + i) * SSTR + coff + j];
            #pragma unroll
            for (int dd = 0; dd < 4; dd++) {
                ulonglong2 vt = *(ulonglong2*)&sKV[(txx + 16 * dd) * VS + jloc0 + j];
                #pragma unroll
                for (int i = 0; i < 4; i++) {
                    ffma2(oacc[i][dd], pv[i].x, vt.x);
                    ffma2(oacc[i][dd], pv[i].y, vt.y);
                }
            }
        }
    }

    float val[4][4];
    #pragma unroll
    for (int i = 0; i < 4; i++)
        #pragma unroll
        for (int dd = 0; dd < 4; dd++) {
            float2 p = unpk(oacc[i][dd]);
            val[i][dd] = p.x + p.y;
        }

    float* sRed = sQ;
    __syncthreads();
    if (g == 1) {
        #pragma unroll
        for (int i = 0; i < 4; i++)
            #pragma unroll
            for (int dd = 0; dd < 4; dd++)
                sRed[(ty * 4 + i) * QS + txx + 16 * dd] = val[i][dd];
    }
    __syncthreads();
    if (g == 0) {
        float* base = g_ctx + ((size_t)(b * SEQ + q0)) * DMODEL + h * DK;
        #pragma unroll
        for (int i = 0; i < 4; i++)
            #pragma unroll
            for (int dd = 0; dd < 4; dd++)
                base[(size_t)(ty * 4 + i) * DMODEL + txx + 16 * dd] =
                    val[i][dd] + sRed[(ty * 4 + i) * QS + txx + 16 * dd];
    }
}

// ==================== launch ====================
extern "C" void kernel_launch(void* const* d_in, const int* in_sizes, int n_in,
                              void* d_out, int out_size) {
    const float* q  = (const float*)d_in[0];
    const float* k  = (const float*)d_in[1];
    const float* v  = (const float*)d_in[2];
    const float* Wq = (const float*)d_in[3];
    const float* bq = (const float*)d_in[4];
    const float* Wk = (const float*)d_in[5];
    const float* bk = (const float*)d_in[6];
    const float* Wv = (const float*)d_in[7];
    const float* bv = (const float*)d_in[8];
    const float* Wo = (const float*)d_in[9];
    const float* bo = (const float*)d_in[10];

    float *gq, *gk, *gv, *gctx;
    __nv_bfloat16 *wth, *wtl;
    cudaGetSymbolAddress((void**)&gq,   g_q);
    cudaGetSymbolAddress((void**)&gk,   g_k);
    cudaGetSymbolAddress((void**)&gv,   g_v);
    cudaGetSymbolAddress((void**)&gctx, g_ctx);
    cudaGetSymbolAddress((void**)&wth,  g_wt_hi);
    cudaGetSymbolAddress((void**)&wtl,  g_wt_lo);

    const int ATTN_SMEM = (64 * QS + CH * QS + 64 * SSTR) * sizeof(float);  // 217088
    const int GEMM_SMEM = 2 * 32768;                                        // 65536
    cudaFuncSetAttribute(attn_tile, cudaFuncAttributeMaxDynamicSharedMemorySize, ATTN_SMEM);
    cudaFuncSetAttribute(gemm_mma_qkv, cudaFuncAttributeMaxDynamicSharedMemorySize, GEMM_SMEM);
    cudaFuncSetAttribute(gemm_mma_one, cudaFuncAttributeMaxDynamicSharedMemorySize, GEMM_SMEM);

    // ---- prep weights (transpose + hi/lo split) ----
    WPrep wp;
    wp.w[0] = Wq; wp.w[1] = Wk; wp.w[2] = Wv; wp.w[3] = Wo;
    dim3 pgrid(DMODEL / 32, DMODEL / 32, 4);
    prep_w<<<pgrid, 256>>>(wp, wth, wtl);

    // ---- QKV projections (HMMA split-bf16) ----
    GemmJob job;
    job.A[0] = q;  job.A[1] = k;  job.A[2] = v;
    const size_t WSZ = (size_t)DMODEL * DMODEL;
    job.Bh[0] = wth;           job.Bl[0] = wtl;
    job.Bh[1] = wth + WSZ;     job.Bl[1] = wtl + WSZ;
    job.Bh[2] = wth + 2 * WSZ; job.Bl[2] = wtl + 2 * WSZ;
    job.bias[0] = bq; job.bias[1] = bk; job.bias[2] = bv;
    job.C[0] = gq; job.C[1] = gk; job.C[2] = gv;

    dim3 ggrid(DMODEL / 128, (BATCH * SEQ) / 128, 3);
    gemm_mma_qkv<<<ggrid, 256, GEMM_SMEM>>>(job);

    // ---- attention ----
    const size_t OUTE  = (size_t)BATCH * SEQ * DMODEL;
    const size_t ATTNE = (size_t)BATCH * NHEADS * SEQ * SEQ;
    float* outp  = (float*)d_out;
    float* attnp = ((size_t)out_size >= OUTE + ATTNE) ? (outp + OUTE) : nullptr;

    dim3 agrid(SEQ / TQ, NHEADS, BATCH);
    attn_tile<<<agrid, 512, ATTN_SMEM>>>(attnp);

    // ---- output projection ----
    dim3 ogrid(DMODEL / 128, (BATCH * SEQ) / 128);
    gemm_mma_one<<<ogrid, 256, GEMM_SMEM>>>(gctx, wth + 3 * WSZ, wtl + 3 * WSZ, bo, outp);
}

// round 7
// speedup vs baseline: 5.8607x; 1.3734x over previous
#include <cuda_runtime.h>
#include <cuda_bf16.h>
#include <math.h>
#include <stdint.h>

#define BATCH  2
#define SEQ    2048
#define DMODEL 1024
#define NHEADS 16
#define DK     64
#define WIN    256

// -------- scratch (allocation-free rule: __device__ globals) --------
__device__ float g_q[BATCH * SEQ * DMODEL];
__device__ float g_k[BATCH * SEQ * DMODEL];
__device__ float g_v[BATCH * SEQ * DMODEL];
__device__ float g_ctx[BATCH * SEQ * DMODEL];
// transposed+split weights: [4][N=1024][K=1024] bf16
__device__ __nv_bfloat16 g_wt_hi[4 * DMODEL * DMODEL];
__device__ __nv_bfloat16 g_wt_lo[4 * DMODEL * DMODEL];

// -------- baseline tensor-core helpers (sm_80+ PTX, safe on sm_103) --------
__device__ __forceinline__ uint32_t s2u(const void* p) {
    uint32_t a;
    asm("{ .reg .u64 t; cvta.to.shared.u64 t, %1; cvt.u32.u64 %0, t; }"
        : "=r"(a) : "l"(p));
    return a;
}
__device__ __forceinline__ void ldmx4(uint32_t* r, uint32_t addr) {
    asm volatile("ldmatrix.sync.aligned.m8n8.x4.shared.b16 {%0,%1,%2,%3}, [%4];"
                 : "=r"(r[0]), "=r"(r[1]), "=r"(r[2]), "=r"(r[3]) : "r"(addr));
}
__device__ __forceinline__ void ldmx2(uint32_t* r, uint32_t addr) {
    asm volatile("ldmatrix.sync.aligned.m8n8.x2.shared.b16 {%0,%1}, [%2];"
                 : "=r"(r[0]), "=r"(r[1]) : "r"(addr));
}
__device__ __forceinline__ void ldmx2t(uint32_t* r, uint32_t addr) {
    asm volatile("ldmatrix.sync.aligned.m8n8.x2.trans.shared.b16 {%0,%1}, [%2];"
                 : "=r"(r[0]), "=r"(r[1]) : "r"(addr));
}
__device__ __forceinline__ void mma_bf16(float* c, const uint32_t* a, const uint32_t* b) {
    asm volatile(
        "mma.sync.aligned.m16n8k16.row.col.f32.bf16.bf16.f32 "
        "{%0,%1,%2,%3}, {%4,%5,%6,%7}, {%8,%9}, {%0,%1,%2,%3};"
        : "+f"(c[0]), "+f"(c[1]), "+f"(c[2]), "+f"(c[3])
        : "r"(a[0]), "r"(a[1]), "r"(a[2]), "r"(a[3]), "r"(b[0]), "r"(b[1]));
}
#define CP_ASYNC16(dst, src) \
    asm volatile("cp.async.ca.shared.global [%0], [%1], 16;" :: "r"(dst), "l"(src))
#define CP_COMMIT()  asm volatile("cp.async.commit_group;" ::: "memory")
#define CP_WAIT0()   asm volatile("cp.async.wait_group 0;" ::: "memory")

__device__ __forceinline__ uint32_t hi_pack(float a, float b) {
    return __byte_perm(__float_as_uint(a), __float_as_uint(b), 0x7632);
}
__device__ __forceinline__ uint32_t lo_pack(float a, float b) {
    float ra = a - __uint_as_float(__float_as_uint(a) & 0xffff0000u);
    float rb = b - __uint_as_float(__float_as_uint(b) & 0xffff0000u);
    __nv_bfloat162 p = __floats2bfloat162_rn(ra, rb);
    return *(uint32_t*)&p;
}

// ==================== weight prep: Wt[n,k] = W[k,n], split hi/lo bf16 ====================
struct WPrep { const float* w[4]; };

__global__ __launch_bounds__(256)
void prep_w(WPrep wp, __nv_bfloat16* __restrict__ hi, __nv_bfloat16* __restrict__ lo) {
    __shared__ float t[32][33];
    const int wi = blockIdx.z;
    const float* W = wp.w[wi];
    const int n0 = blockIdx.x * 32, k0 = blockIdx.y * 32;
    const int tx = threadIdx.x & 31, ty = (threadIdx.x >> 5) * 4;
    #pragma unroll
    for (int i = 0; i < 4; i++)
        t[ty + i][tx] = W[(size_t)(k0 + ty + i) * DMODEL + n0 + tx];
    __syncthreads();
    #pragma unroll
    for (int i = 0; i < 4; i++) {
        float a = t[tx][ty + i];
        __nv_bfloat16 h = __float2bfloat16_rz(a);
        float hf = __bfloat162float(h);
        __nv_bfloat16 l = __float2bfloat16(a - hf);
        size_t idx = (size_t)wi * DMODEL * DMODEL + (size_t)(n0 + ty + i) * DMODEL + k0 + tx;
        hi[idx] = h;
        lo[idx] = l;
    }
}

// ==================== HMMA split-bf16 GEMM: C = A @ W + bias ====================
struct GemmJob {
    const float* A[3];
    const __nv_bfloat16* Bh[3];
    const __nv_bfloat16* Bl[3];
    const float* bias[3];
    float* C[3];
};

__device__ __forceinline__
void gemm_mma_body(const float* __restrict__ A, const __nv_bfloat16* __restrict__ Bh,
                   const __nv_bfloat16* __restrict__ Bl, const float* __restrict__ bias,
                   float* __restrict__ C) {
    extern __shared__ char smx[];
    const int tid = threadIdx.x, lane = tid & 31, wid = tid >> 5;
    const int brow = blockIdx.y << 7, bcol = blockIdx.x << 7;
    const int wm = (wid >> 2) << 6;
    const int wn = (wid & 3) << 5;

    const uint32_t sbase = s2u(smx);

    float acc[4][4][4];
    #pragma unroll
    for (int i = 0; i < 4; i++)
        #pragma unroll
        for (int j = 0; j < 4; j++)
            #pragma unroll
            for (int u = 0; u < 4; u++) acc[i][j][u] = 0.f;

    {
        #pragma unroll
        for (int it = 0; it < 2; it++) {
            int f = tid + it * 256;
            int row = f >> 2, grp = f & 3;
            const __nv_bfloat16* srcH = Bh + (size_t)(bcol + row) * DMODEL + grp * 8;
            const __nv_bfloat16* srcL = Bl + (size_t)(bcol + row) * DMODEL + grp * 8;
            uint32_t dH = sbase + 16384u + row * 128 + ((grp ^ (row & 7)) << 4);
            uint32_t dL = sbase + 16384u + row * 128 + (((grp + 4) ^ (row & 7)) << 4);
            CP_ASYNC16(dH, srcH);
            CP_ASYNC16(dL, srcL);
        }
        CP_COMMIT();
        #pragma unroll
        for (int it = 0; it < 2; it++) {
            int f = tid + it * 256;
            int row = f >> 2, grp = f & 3;
            const float* ap = A + (size_t)(brow + row) * DMODEL + grp * 8;
            float4 f0 = *(const float4*)ap, f1 = *(const float4*)(ap + 4);
            uint4 ah = make_uint4(hi_pack(f0.x, f0.y), hi_pack(f0.z, f0.w),
                                  hi_pack(f1.x, f1.y), hi_pack(f1.z, f1.w));
            uint4 al = make_uint4(lo_pack(f0.x, f0.y), lo_pack(f0.z, f0.w),
                                  lo_pack(f1.x, f1.y), lo_pack(f1.z, f1.w));
            *(uint4*)(smx + row * 128 + ((grp ^ (row & 7)) << 4)) = ah;
            *(uint4*)(smx + row * 128 + (((grp + 4) ^ (row & 7)) << 4)) = al;
        }
        CP_WAIT0();
        __syncthreads();
    }

    for (int kt = 0; kt < 32; kt++) {
        const int s = kt & 1;
        const uint32_t soff = (uint32_t)s << 15;

        float4 pf[2][2];
        if (kt < 31) {
            const int k0 = (kt + 1) << 5;
            const uint32_t noff = (uint32_t)(s ^ 1) << 15;
            #pragma unroll
            for (int it = 0; it < 2; it++) {
                int f = tid + it * 256;
                int row = f >> 2, grp = f & 3;
                const __nv_bfloat16* srcH = Bh + (size_t)(bcol + row) * DMODEL + k0 + grp * 8;
                const __nv_bfloat16* srcL = Bl + (size_t)(bcol + row) * DMODEL + k0 + grp * 8;
                uint32_t dH = sbase + noff + 16384u + row * 128 + ((grp ^ (row & 7)) << 4);
                uint32_t dL = sbase + noff + 16384u + row * 128 + (((grp + 4) ^ (row & 7)) << 4);
                CP_ASYNC16(dH, srcH);
                CP_ASYNC16(dL, srcL);
                const float* ap = A + (size_t)(brow + row) * DMODEL + k0 + grp * 8;
                pf[it][0] = *(const float4*)ap;
                pf[it][1] = *(const float4*)(ap + 4);
            }
            CP_COMMIT();
        }

        const uint32_t aBase = sbase + soff;
        const uint32_t bBase = sbase + soff + 16384u;
        #pragma unroll
        for (int ks2 = 0; ks2 < 2; ks2++) {
            uint32_t aH[4][4], aL[4][4], bH[4][2], bL[4][2];
            const int cA = (ks2 << 1) + (lane >> 4);
            #pragma unroll
            for (int i = 0; i < 4; i++) {
                int r = wm + i * 16 + (lane & 15);
                ldmx4(aH[i], aBase + r * 128 + ((cA ^ (r & 7)) << 4));
                ldmx4(aL[i], aBase + r * 128 + (((cA + 4) ^ (r & 7)) << 4));
            }
            const int cB = (ks2 << 1) + ((lane >> 3) & 1);
            #pragma unroll
            for (int j = 0; j < 4; j++) {
                int rn = wn + j * 8 + (lane & 7);
                ldmx2(bH[j], bBase + rn * 128 + ((cB ^ (rn & 7)) << 4));
                ldmx2(bL[j], bBase + rn * 128 + (((cB + 4) ^ (rn & 7)) << 4));
            }
            #pragma unroll
            for (int i = 0; i < 4; i++)
                #pragma unroll
                for (int j = 0; j < 4; j++) {
                    mma_bf16(acc[i][j], aH[i], bH[j]);
                    mma_bf16(acc[i][j], aH[i], bL[j]);
                    mma_bf16(acc[i][j], aL[i], bH[j]);
                }
        }

        if (kt < 31) {
            const uint32_t noff = (uint32_t)(s ^ 1) << 15;
            #pragma unroll
            for (int it = 0; it < 2; it++) {
                int f = tid + it * 256;
                int row = f >> 2, grp = f & 3;
                float4 f0 = pf[it][0], f1 = pf[it][1];
                uint4 ah = make_uint4(hi_pack(f0.x, f0.y), hi_pack(f0.z, f0.w),
                                      hi_pack(f1.x, f1.y), hi_pack(f1.z, f1.w));
                uint4 al = make_uint4(lo_pack(f0.x, f0.y), lo_pack(f0.z, f0.w),
                                      lo_pack(f1.x, f1.y), lo_pack(f1.z, f1.w));
                *(uint4*)(smx + noff + row * 128 + ((grp ^ (row & 7)) << 4)) = ah;
                *(uint4*)(smx + noff + row * 128 + (((grp + 4) ^ (row & 7)) << 4)) = al;
            }
            CP_WAIT0();
        }
        __syncthreads();
    }

    const int g = lane >> 2, tg = lane & 3;
    #pragma unroll
    for (int i = 0; i < 4; i++) {
        const int r0 = brow + wm + i * 16 + g;
        #pragma unroll
        for (int j = 0; j < 4; j++) {
            const int col = bcol + wn + j * 8 + tg * 2;
            float2 bb = *(const float2*)(bias + col);
            float2 o0 = make_float2(acc[i][j][0] + bb.x, acc[i][j][1] + bb.y);
            float2 o1 = make_float2(acc[i][j][2] + bb.x, acc[i][j][3] + bb.y);
            *(float2*)(C + (size_t)r0 * DMODEL + col)       = o0;
            *(float2*)(C + (size_t)(r0 + 8) * DMODEL + col) = o1;
        }
    }
}

__global__ __launch_bounds__(256, 2)
void gemm_mma_qkv(GemmJob job) {
    const int z = blockIdx.z;
    gemm_mma_body(job.A[z], job.Bh[z], job.Bl[z], job.bias[z], job.C[z]);
}

__global__ __launch_bounds__(256, 2)
void gemm_mma_one(const float* __restrict__ A, const __nv_bfloat16* __restrict__ Bh,
                  const __nv_bfloat16* __restrict__ Bl, const float* __restrict__ bias,
                  float* __restrict__ C) {
    gemm_mma_body(A, Bh, Bl, bias, C);
}

// ==================== HMMA sliding-window attention ====================
// 256 threads / 8 warps per (b, h, 64-query tile). 2-pass flash-style:
// pass1 QK -> online (m,l) per row per 64-key half; merge; pass2 recompute
// QK, normalize p in fragments, write dense attn, p->bf16 smem, AV mma.
// smem (bytes): Qh 0..8K, Ql 8K..16K, Kh 16K..32K (alias Ph), Kl 32K..48K
// (alias Pl), Vh 48K..64K? -> layout below. total 83,968 B.
#define SQH 0
#define SQL 8192
#define SKH 16384
#define SKL 32768
#define SVH 49152
#define SVL 65536
#define SMP 81920
#define SLP 82432
#define ATTN_SMEM_B 83968

// load 128 seq rows of [64 d] fp32 -> bf16 hi/lo swizzled tiles
__device__ __forceinline__
void load_seq128(const float* __restrict__ src, char* dh, char* dl,
                 int b, int h, int kbase, int hi_idx, int tid) {
    #pragma unroll
    for (int it = 0; it < 4; it++) {
        int f = tid + it * 256;             // 0..1023
        int r = f >> 3, gr = f & 7;
        int kr = kbase + r;
        float4 f0 = make_float4(0.f, 0.f, 0.f, 0.f), f1 = f0;
        if (kr <= hi_idx) {
            const float* p = src + ((size_t)(b * SEQ + kr)) * DMODEL + h * DK + gr * 8;
            f0 = *(const float4*)p;
            f1 = *(const float4*)(p + 4);
        }
        uint4 hh = make_uint4(hi_pack(f0.x, f0.y), hi_pack(f0.z, f0.w),
                              hi_pack(f1.x, f1.y), hi_pack(f1.z, f1.w));
        uint4 ll = make_uint4(lo_pack(f0.x, f0.y), lo_pack(f0.z, f0.w),
                              lo_pack(f1.x, f1.y), lo_pack(f1.z, f1.w));
        int off = r * 128 + ((gr ^ (r & 7)) << 4);
        *(uint4*)(dh + off) = hh;
        *(uint4*)(dl + off) = ll;
    }
}

// QK^T for this warp's 16 q-rows x 64-key half -> acc[8][4]
__device__ __forceinline__
void qk_mma(float acc[8][4], uint32_t qh, uint32_t ql, uint32_t kh, uint32_t kl,
            int wm, int wnh, int lane) {
    #pragma unroll
    for (int j = 0; j < 8; j++)
        #pragma unroll
        for (int u = 0; u < 4; u++) acc[j][u] = 0.f;
    #pragma unroll
    for (int ks = 0; ks < 4; ks++) {
        uint32_t aH[4], aL[4];
        int ar = wm + (lane & 15);
        int cA = ks * 2 + (lane >> 4);
        uint32_t aoff = ar * 128 + ((cA ^ (ar & 7)) << 4);
        ldmx4(aH, qh + aoff);
        ldmx4(aL, ql + aoff);
        #pragma unroll
        for (int j = 0; j < 8; j++) {
            int rn = wnh * 64 + j * 8 + (lane & 7);
            int cB = ks * 2 + ((lane >> 3) & 1);
            uint32_t boff = rn * 128 + ((cB ^ (rn & 7)) << 4);
            uint32_t bH[2], bL[2];
            ldmx2(bH, kh + boff);
            ldmx2(bL, kl + boff);
            mma_bf16(acc[j], aH, bH);
            mma_bf16(acc[j], aH, bL);
            mma_bf16(acc[j], aL, bH);
        }
    }
}

__global__ __launch_bounds__(256, 2)
void attn_mma(float* __restrict__ attnp) {
    extern __shared__ char sax[];
    float* sMp = (float*)(sax + SMP);
    float* sLp = (float*)(sax + SLP);

    const int qt = blockIdx.x, h = blockIdx.y, b = blockIdx.z;
    const int q0 = qt * 64;
    const int tid = threadIdx.x, lane = tid & 31, w = tid >> 5;
    const int wm = (w >> 1) << 4;       // 0,16,32,48
    const int wnh = w & 1;              // key half (QK) / d half (AV)
    const int g = lane >> 2, tg = lane & 3;

    const int lo  = max(0, q0 - WIN);
    const int hi  = min(SEQ - 1, q0 + 63 + WIN);
    const int cnt = hi - lo + 1;
    const int nch = (cnt + 127) >> 7;

    const uint32_t qh = s2u(sax) + SQH, ql = s2u(sax) + SQL;
    const uint32_t kh = s2u(sax) + SKH, kl = s2u(sax) + SKL;
    const uint32_t vh = s2u(sax) + SVH, vl = s2u(sax) + SVL;

    // ---- load Q tile -> bf16 hi/lo ----
    {
        const float* qb = g_q + ((size_t)(b * SEQ + q0)) * DMODEL + h * DK;
        #pragma unroll
        for (int it = 0; it < 2; it++) {
            int f = tid + it * 256;        // 0..511
            int r = f >> 3, gr = f & 7;
            const float* p = qb + (size_t)r * DMODEL + gr * 8;
            float4 f0 = *(const float4*)p, f1 = *(const float4*)(p + 4);
            uint4 hh = make_uint4(hi_pack(f0.x, f0.y), hi_pack(f0.z, f0.w),
                                  hi_pack(f1.x, f1.y), hi_pack(f1.z, f1.w));
            uint4 ll = make_uint4(lo_pack(f0.x, f0.y), lo_pack(f0.z, f0.w),
                                  lo_pack(f1.x, f1.y), lo_pack(f1.z, f1.w));
            int off = r * 128 + ((gr ^ (r & 7)) << 4);
            *(uint4*)(sax + SQH + off) = hh;
            *(uint4*)(sax + SQL + off) = ll;
        }
    }

    const int qg0 = q0 + wm + g, qg1 = qg0 + 8;
    const int jlo0 = max(lo, qg0 - WIN), jhi0 = min(hi, qg0 + WIN);
    const int jlo1 = max(lo, qg1 - WIN), jhi1 = min(hi, qg1 + WIN);

    // ---- pass 1: online (m, l) per row over this warp's key half ----
    float m0 = -1e30f, m1 = -1e30f, l0 = 0.f, l1 = 0.f;
    for (int c = 0; c < nch; c++) {
        __syncthreads();
        load_seq128(g_k, sax + SKH, sax + SKL, b, h, lo + c * 128, hi, tid);
        __syncthreads();
        float acc[8][4];
        qk_mma(acc, qh, ql, kh, kl, wm, wnh, lane);

        const int cb = lo + c * 128 + wnh * 64;
        float cmax0 = -1e30f, cmax1 = -1e30f;
        #pragma unroll
        for (int j = 0; j < 8; j++) {
            int jg = cb + j * 8 + tg * 2;
            #pragma unroll
            for (int u = 0; u < 4; u++) acc[j][u] *= 0.125f;
            if (jg     >= jlo0 && jg     <= jhi0) cmax0 = fmaxf(cmax0, acc[j][0]);
            if (jg + 1 >= jlo0 && jg + 1 <= jhi0) cmax0 = fmaxf(cmax0, acc[j][1]);
            if (jg     >= jlo1 && jg     <= jhi1) cmax1 = fmaxf(cmax1, acc[j][2]);
            if (jg + 1 >= jlo1 && jg + 1 <= jhi1) cmax1 = fmaxf(cmax1, acc[j][3]);
        }
        cmax0 = fmaxf(cmax0, __shfl_xor_sync(0xffffffffu, cmax0, 1));
        cmax0 = fmaxf(cmax0, __shfl_xor_sync(0xffffffffu, cmax0, 2));
        cmax1 = fmaxf(cmax1, __shfl_xor_sync(0xffffffffu, cmax1, 1));
        cmax1 = fmaxf(cmax1, __shfl_xor_sync(0xffffffffu, cmax1, 2));

        float mn0 = fmaxf(m0, cmax0), mn1 = fmaxf(m1, cmax1);
        float s0 = 0.f, s1 = 0.f;
        #pragma unroll
        for (int j = 0; j < 8; j++) {
            int jg = cb + j * 8 + tg * 2;
            if (jg     >= jlo0 && jg     <= jhi0) s0 += __expf(acc[j][0] - mn0);
            if (jg + 1 >= jlo0 && jg + 1 <= jhi0) s0 += __expf(acc[j][1] - mn0);
            if (jg     >= jlo1 && jg     <= jhi1) s1 += __expf(acc[j][2] - mn1);
            if (jg + 1 >= jlo1 && jg + 1 <= jhi1) s1 += __expf(acc[j][3] - mn1);
        }
        s0 += __shfl_xor_sync(0xffffffffu, s0, 1);
        s0 += __shfl_xor_sync(0xffffffffu, s0, 2);
        s1 += __shfl_xor_sync(0xffffffffu, s1, 1);
        s1 += __shfl_xor_sync(0xffffffffu, s1, 2);

        l0 = (m0 > -1e29f ? l0 * __expf(m0 - mn0) : 0.f) + s0;
        l1 = (m1 > -1e29f ? l1 * __expf(m1 - mn1) : 0.f) + s1;
        m0 = mn0; m1 = mn1;
    }

    // ---- merge the two key halves ----
    if (tg == 0) {
        sMp[wnh * 64 + wm + g]     = m0;  sLp[wnh * 64 + wm + g]     = l0;
        sMp[wnh * 64 + wm + g + 8] = m1;  sLp[wnh * 64 + wm + g + 8] = l1;
    }
    __syncthreads();
    float mf0, mf1, li0, li1;
    {
        int r0 = wm + g, r1 = r0 + 8;
        float ma = sMp[r0], mb2 = sMp[64 + r0];
        float la = sLp[r0], lb2 = sLp[64 + r0];
        mf0 = fmaxf(ma, mb2);
        li0 = 1.f / (la * __expf(ma - mf0) + lb2 * __expf(mb2 - mf0));
        ma = sMp[r1]; mb2 = sMp[64 + r1];
        la = sLp[r1]; lb2 = sLp[64 + r1];
        mf1 = fmaxf(ma, mb2);
        li1 = 1.f / (la * __expf(ma - mf1) + lb2 * __expf(mb2 - mf1));
    }

    // ---- zero-fill attn outside band chunks ----
    float* baseA = nullptr;
    if (attnp) {
        baseA = attnp + ((size_t)((b * NHEADS + h) * SEQ + q0)) * SEQ;
        const int z2 = min((int)SEQ, lo + nch * 128);
        for (int f = tid; f < 64 * 512; f += 256) {
            int m = f >> 9, c4 = (f & 511) << 2;
            if (c4 < lo || c4 >= z2)
                *(float4*)(baseA + (size_t)m * SEQ + c4) = make_float4(0.f, 0.f, 0.f, 0.f);
        }
    }

    // ---- pass 2: recompute QK, normalize, write attn, p->smem, AV ----
    float oacc[4][4];
    #pragma unroll
    for (int j = 0; j < 4; j++)
        #pragma unroll
        for (int u = 0; u < 4; u++) oacc[j][u] = 0.f;

    for (int c = 0; c < nch; c++) {
        __syncthreads();
        load_seq128(g_k, sax + SKH, sax + SKL, b, h, lo + c * 128, hi, tid);
        load_seq128(g_v, sax + SVH, sax + SVL, b, h, lo + c * 128, hi, tid);
        __syncthreads();
        float acc[8][4];
        qk_mma(acc, qh, ql, kh, kl, wm, wnh, lane);

        const int cb = lo + c * 128 + wnh * 64;
        #pragma unroll
        for (int j = 0; j < 8; j++) {
            int jg = cb + j * 8 + tg * 2;
            float p0 = (jg     >= jlo0 && jg     <= jhi0) ? __expf(acc[j][0] * 0.125f - mf0) * li0 : 0.f;
            float p1 = (jg + 1 >= jlo0 && jg + 1 <= jhi0) ? __expf(acc[j][1] * 0.125f - mf0) * li0 : 0.f;
            float p2 = (jg     >= jlo1 && jg     <= jhi1) ? __expf(acc[j][2] * 0.125f - mf1) * li1 : 0.f;
            float p3 = (jg + 1 >= jlo1 && jg + 1 <= jhi1) ? __expf(acc[j][3] * 0.125f - mf1) * li1 : 0.f;
            acc[j][0] = p0; acc[j][1] = p1; acc[j][2] = p2; acc[j][3] = p3;
            if (baseA && jg < SEQ) {
                *(float2*)(baseA + (size_t)(wm + g) * SEQ + jg)     = make_float2(p0, p1);
                *(float2*)(baseA + (size_t)(wm + g + 8) * SEQ + jg) = make_float2(p2, p3);
            }
        }
        __syncthreads();   // all warps done reading sK before aliasing as sP

        // p -> bf16 hi/lo into sP (= sK buffers), two [64][64] subtiles
        #pragma unroll
        for (int j = 0; j < 8; j++) {
            int col = wnh * 64 + j * 8 + tg * 2;
            int sub = col >> 6, c64 = col & 63;
            int r0 = wm + g, r1 = r0 + 8;
            int o0 = sub * 8192 + r0 * 128 + ((((c64 >> 3)) ^ (r0 & 7)) << 4) + (c64 & 7) * 2;
            int o1 = sub * 8192 + r1 * 128 + ((((c64 >> 3)) ^ (r1 & 7)) << 4) + (c64 & 7) * 2;
            *(uint32_t*)(sax + SKH + o0) = hi_pack(acc[j][0], acc[j][1]);
            *(uint32_t*)(sax + SKL + o0) = lo_pack(acc[j][0], acc[j][1]);
            *(uint32_t*)(sax + SKH + o1) = hi_pack(acc[j][2], acc[j][3]);
            *(uint32_t*)(sax + SKL + o1) = lo_pack(acc[j][2], acc[j][3]);
        }
        __syncthreads();

        // AV: A = P [16 q x 128 keys], B = V^T via ldmatrix.trans
        #pragma unroll
        for (int ks = 0; ks < 8; ks++) {
            uint32_t aH[4], aL[4];
            int ar = wm + (lane & 15);
            int sub = ks >> 2;
            int cA = (ks & 3) * 2 + (lane >> 4);
            uint32_t aoff = sub * 8192 + ar * 128 + ((cA ^ (ar & 7)) << 4);
            ldmx4(aH, kh + aoff);
            ldmx4(aL, kl + aoff);
            #pragma unroll
            for (int j = 0; j < 4; j++) {
                int rv = ks * 16 + (lane & 7) + ((lane >> 3) & 1) * 8;
                int gd = wnh * 4 + j;
                uint32_t boff = rv * 128 + ((gd ^ (rv & 7)) << 4);
                uint32_t bH[2], bL[2];
                ldmx2t(bH, vh + boff);
                ldmx2t(bL, vl + boff);
                mma_bf16(oacc[j], aH, bH);
                mma_bf16(oacc[j], aH, bL);
                mma_bf16(oacc[j], aL, bH);
            }
        }
    }

    // ---- write ctx ----
    {
        float* cb2 = g_ctx + ((size_t)(b * SEQ + q0 + wm + g)) * DMODEL + h * DK + wnh * 32;
        #pragma unroll
        for (int j = 0; j < 4; j++) {
            int col = j * 8 + tg * 2;
            *(float2*)(cb2 + col)              = make_float2(oacc[j][0], oacc[j][1]);
            *(float2*)(cb2 + 8 * DMODEL + col) = make_float2(oacc[j][2], oacc[j][3]);
        }
    }
}

// ==================== launch ====================
extern "C" void kernel_launch(void* const* d_in, const int* in_sizes, int n_in,
                              void* d_out, int out_size) {
    const float* q  = (const float*)d_in[0];
    const float* k  = (const float*)d_in[1];
    const float* v  = (const float*)d_in[2];
    const float* Wq = (const float*)d_in[3];
    const float* bq = (const float*)d_in[4];
    const float* Wk = (const float*)d_in[5];
    const float* bk = (const float*)d_in[6];
    const float* Wv = (const float*)d_in[7];
    const float* bv = (const float*)d_in[8];
    const float* Wo = (const float*)d_in[9];
    const float* bo = (const float*)d_in[10];

    float *gq, *gk, *gv, *gctx;
    __nv_bfloat16 *wth, *wtl;
    cudaGetSymbolAddress((void**)&gq,   g_q);
    cudaGetSymbolAddress((void**)&gk,   g_k);
    cudaGetSymbolAddress((void**)&gv,   g_v);
    cudaGetSymbolAddress((void**)&gctx, g_ctx);
    cudaGetSymbolAddress((void**)&wth,  g_wt_hi);
    cudaGetSymbolAddress((void**)&wtl,  g_wt_lo);

    const int GEMM_SMEM = 2 * 32768;
    cudaFuncSetAttribute(gemm_mma_qkv, cudaFuncAttributeMaxDynamicSharedMemorySize, GEMM_SMEM);
    cudaFuncSetAttribute(gemm_mma_one, cudaFuncAttributeMaxDynamicSharedMemorySize, GEMM_SMEM);
    cudaFuncSetAttribute(attn_mma, cudaFuncAttributeMaxDynamicSharedMemorySize, ATTN_SMEM_B);

    // ---- prep weights (transpose + hi/lo split) ----
    WPrep wp;
    wp.w[0] = Wq; wp.w[1] = Wk; wp.w[2] = Wv; wp.w[3] = Wo;
    dim3 pgrid(DMODEL / 32, DMODEL / 32, 4);
    prep_w<<<pgrid, 256>>>(wp, wth, wtl);

    // ---- QKV projections ----
    GemmJob job;
    job.A[0] = q;  job.A[1] = k;  job.A[2] = v;
    const size_t WSZ = (size_t)DMODEL * DMODEL;
    job.Bh[0] = wth;           job.Bl[0] = wtl;
    job.Bh[1] = wth + WSZ;     job.Bl[1] = wtl + WSZ;
    job.Bh[2] = wth + 2 * WSZ; job.Bl[2] = wtl + 2 * WSZ;
    job.bias[0] = bq; job.bias[1] = bk; job.bias[2] = bv;
    job.C[0] = gq; job.C[1] = gk; job.C[2] = gv;

    dim3 ggrid(DMODEL / 128, (BATCH * SEQ) / 128, 3);
    gemm_mma_qkv<<<ggrid, 256, GEMM_SMEM>>>(job);

    // ---- attention ----
    const size_t OUTE  = (size_t)BATCH * SEQ * DMODEL;
    const size_t ATTNE = (size_t)BATCH * NHEADS * SEQ * SEQ;
    float* outp  = (float*)d_out;
    float* attnp = ((size_t)out_size >= OUTE + ATTNE) ? (outp + OUTE) : nullptr;

    dim3 agrid(SEQ / 64, NHEADS, BATCH);
    attn_mma<<<agrid, 256, ATTN_SMEM_B>>>(attnp);

    // ---- output projection ----
    dim3 ogrid(DMODEL / 128, (BATCH * SEQ) / 128);
    gemm_mma_one<<<ogrid, 256, GEMM_SMEM>>>(gctx, wth + 3 * WSZ, wtl + 3 * WSZ, bo, outp);
}

// round 8
// speedup vs baseline: 6.0010x; 1.0239x over previous
#include <cuda_runtime.h>
#include <cuda_bf16.h>
#include <math.h>
#include <stdint.h>

#define BATCH  2
#define SEQ    2048
#define DMODEL 1024
#define NHEADS 16
#define DK     64
#define WIN    256

// -------- scratch (allocation-free rule: __device__ globals) --------
__device__ float g_q[BATCH * SEQ * DMODEL];
__device__ float g_k[BATCH * SEQ * DMODEL];
__device__ float g_v[BATCH * SEQ * DMODEL];
__device__ float g_ctx[BATCH * SEQ * DMODEL];
// transposed+split weights: [4][N=1024][K=1024] bf16
__device__ __nv_bfloat16 g_wt_hi[4 * DMODEL * DMODEL];
__device__ __nv_bfloat16 g_wt_lo[4 * DMODEL * DMODEL];

// -------- baseline tensor-core helpers (sm_80+ PTX, safe on sm_103) --------
__device__ __forceinline__ uint32_t s2u(const void* p) {
    uint32_t a;
    asm("{ .reg .u64 t; cvta.to.shared.u64 t, %1; cvt.u32.u64 %0, t; }"
        : "=r"(a) : "l"(p));
    return a;
}
__device__ __forceinline__ void ldmx4(uint32_t* r, uint32_t addr) {
    asm volatile("ldmatrix.sync.aligned.m8n8.x4.shared.b16 {%0,%1,%2,%3}, [%4];"
                 : "=r"(r[0]), "=r"(r[1]), "=r"(r[2]), "=r"(r[3]) : "r"(addr));
}
__device__ __forceinline__ void ldmx4t(uint32_t* r, uint32_t addr) {
    asm volatile("ldmatrix.sync.aligned.m8n8.x4.trans.shared.b16 {%0,%1,%2,%3}, [%4];"
                 : "=r"(r[0]), "=r"(r[1]), "=r"(r[2]), "=r"(r[3]) : "r"(addr));
}
__device__ __forceinline__ void mma_bf16(float* c, const uint32_t* a, const uint32_t* b) {
    asm volatile(
        "mma.sync.aligned.m16n8k16.row.col.f32.bf16.bf16.f32 "
        "{%0,%1,%2,%3}, {%4,%5,%6,%7}, {%8,%9}, {%0,%1,%2,%3};"
        : "+f"(c[0]), "+f"(c[1]), "+f"(c[2]), "+f"(c[3])
        : "r"(a[0]), "r"(a[1]), "r"(a[2]), "r"(a[3]), "r"(b[0]), "r"(b[1]));
}
#define CP_ASYNC16(dst, src) \
    asm volatile("cp.async.ca.shared.global [%0], [%1], 16;" :: "r"(dst), "l"(src))
#define CP_COMMIT()  asm volatile("cp.async.commit_group;" ::: "memory")
#define CP_WAIT0()   asm volatile("cp.async.wait_group 0;" ::: "memory")

__device__ __forceinline__ uint32_t hi_pack(float a, float b) {
    return __byte_perm(__float_as_uint(a), __float_as_uint(b), 0x7632);
}
__device__ __forceinline__ uint32_t lo_pack(float a, float b) {
    float ra = a - __uint_as_float(__float_as_uint(a) & 0xffff0000u);
    float rb = b - __uint_as_float(__float_as_uint(b) & 0xffff0000u);
    __nv_bfloat162 p = __floats2bfloat162_rn(ra, rb);
    return *(uint32_t*)&p;
}

// ==================== weight prep: Wt[n,k] = W[k,n], split hi/lo bf16 ====================
struct WPrep { const float* w[4]; };

__global__ __launch_bounds__(256)
void prep_w(WPrep wp, __nv_bfloat16* __restrict__ hi, __nv_bfloat16* __restrict__ lo) {
    __shared__ float t[32][33];
    const int wi = blockIdx.z;
    const float* W = wp.w[wi];
    const int n0 = blockIdx.x * 32, k0 = blockIdx.y * 32;
    const int tx = threadIdx.x & 31, ty = (threadIdx.x >> 5) * 4;
    #pragma unroll
    for (int i = 0; i < 4; i++)
        t[ty + i][tx] = W[(size_t)(k0 + ty + i) * DMODEL + n0 + tx];
    __syncthreads();
    #pragma unroll
    for (int i = 0; i < 4; i++) {
        float a = t[tx][ty + i];
        __nv_bfloat16 h = __float2bfloat16_rz(a);
        float hf = __bfloat162float(h);
        __nv_bfloat16 l = __float2bfloat16(a - hf);
        size_t idx = (size_t)wi * DMODEL * DMODEL + (size_t)(n0 + ty + i) * DMODEL + k0 + tx;
        hi[idx] = h;
        lo[idx] = l;
    }
}

// ==================== HMMA split-bf16 GEMM: C = A @ W + bias ====================
struct GemmJob {
    const float* A[3];
    const __nv_bfloat16* Bh[3];
    const __nv_bfloat16* Bl[3];
    const float* bias[3];
    float* C[3];
};

__device__ __forceinline__
void gemm_mma_body(const float* __restrict__ A, const __nv_bfloat16* __restrict__ Bh,
                   const __nv_bfloat16* __restrict__ Bl, const float* __restrict__ bias,
                   float* __restrict__ C) {
    extern __shared__ char smx[];
    const int tid = threadIdx.x, lane = tid & 31, wid = tid >> 5;
    const int brow = blockIdx.y << 7, bcol = blockIdx.x << 7;
    const int wm = (wid >> 2) << 6;
    const int wn = (wid & 3) << 5;

    const uint32_t sbase = s2u(smx);

    float acc[4][4][4];
    #pragma unroll
    for (int i = 0; i < 4; i++)
        #pragma unroll
        for (int j = 0; j < 4; j++)
            #pragma unroll
            for (int u = 0; u < 4; u++) acc[i][j][u] = 0.f;

    {
        #pragma unroll
        for (int it = 0; it < 2; it++) {
            int f = tid + it * 256;
            int row = f >> 2, grp = f & 3;
            const __nv_bfloat16* srcH = Bh + (size_t)(bcol + row) * DMODEL + grp * 8;
            const __nv_bfloat16* srcL = Bl + (size_t)(bcol + row) * DMODEL + grp * 8;
            uint32_t dH = sbase + 16384u + row * 128 + ((grp ^ (row & 7)) << 4);
            uint32_t dL = sbase + 16384u + row * 128 + (((grp + 4) ^ (row & 7)) << 4);
            CP_ASYNC16(dH, srcH);
            CP_ASYNC16(dL, srcL);
        }
        CP_COMMIT();
        #pragma unroll
        for (int it = 0; it < 2; it++) {
            int f = tid + it * 256;
            int row = f >> 2, grp = f & 3;
            const float* ap = A + (size_t)(brow + row) * DMODEL + grp * 8;
            float4 f0 = *(const float4*)ap, f1 = *(const float4*)(ap + 4);
            uint4 ah = make_uint4(hi_pack(f0.x, f0.y), hi_pack(f0.z, f0.w),
                                  hi_pack(f1.x, f1.y), hi_pack(f1.z, f1.w));
            uint4 al = make_uint4(lo_pack(f0.x, f0.y), lo_pack(f0.z, f0.w),
                                  lo_pack(f1.x, f1.y), lo_pack(f1.z, f1.w));
            *(uint4*)(smx + row * 128 + ((grp ^ (row & 7)) << 4)) = ah;
            *(uint4*)(smx + row * 128 + (((grp + 4) ^ (row & 7)) << 4)) = al;
        }
        CP_WAIT0();
        __syncthreads();
    }

    for (int kt = 0; kt < 32; kt++) {
        const int s = kt & 1;
        const uint32_t soff = (uint32_t)s << 15;

        float4 pf[2][2];
        if (kt < 31) {
            const int k0 = (kt + 1) << 5;
            const uint32_t noff = (uint32_t)(s ^ 1) << 15;
            #pragma unroll
            for (int it = 0; it < 2; it++) {
                int f = tid + it * 256;
                int row = f >> 2, grp = f & 3;
                const __nv_bfloat16* srcH = Bh + (size_t)(bcol + row) * DMODEL + k0 + grp * 8;
                const __nv_bfloat16* srcL = Bl + (size_t)(bcol + row) * DMODEL + k0 + grp * 8;
                uint32_t dH = sbase + noff + 16384u + row * 128 + ((grp ^ (row & 7)) << 4);
                uint32_t dL = sbase + noff + 16384u + row * 128 + (((grp + 4) ^ (row & 7)) << 4);
                CP_ASYNC16(dH, srcH);
                CP_ASYNC16(dL, srcL);
                const float* ap = A + (size_t)(brow + row) * DMODEL + k0 + grp * 8;
                pf[it][0] = *(const float4*)ap;
                pf[it][1] = *(const float4*)(ap + 4);
            }
            CP_COMMIT();
        }

        const uint32_t aBase = sbase + soff;
        const uint32_t bBase = sbase + soff + 16384u;
        #pragma unroll
        for (int ks2 = 0; ks2 < 2; ks2++) {
            uint32_t aH[4][4], aL[4][4];
            const int cA = (ks2 << 1) + (lane >> 4);
            #pragma unroll
            for (int i = 0; i < 4; i++) {
                int r = wm + i * 16 + (lane & 15);
                ldmx4(aH[i], aBase + r * 128 + ((cA ^ (r & 7)) << 4));
                ldmx4(aL[i], aBase + r * 128 + (((cA + 4) ^ (r & 7)) << 4));
            }
            const int cB = (ks2 << 1) + ((lane >> 3) & 1);
            #pragma unroll
            for (int jp = 0; jp < 2; jp++) {
                int rn = wn + jp * 16 + (lane & 7) + ((lane >> 4) & 1) * 8;
                uint32_t bh4[4], bl4[4];
                ldmx4(bh4, bBase + rn * 128 + ((cB ^ (rn & 7)) << 4));
                ldmx4(bl4, bBase + rn * 128 + (((cB + 4) ^ (rn & 7)) << 4));
                #pragma unroll
                for (int i = 0; i < 4; i++) {
                    mma_bf16(acc[i][jp * 2], aH[i], bh4);
                    mma_bf16(acc[i][jp * 2], aH[i], bl4);
                    mma_bf16(acc[i][jp * 2], aL[i], bh4);
                    mma_bf16(acc[i][jp * 2 + 1], aH[i], bh4 + 2);
                    mma_bf16(acc[i][jp * 2 + 1], aH[i], bl4 + 2);
                    mma_bf16(acc[i][jp * 2 + 1], aL[i], bh4 + 2);
                }
            }
        }

        if (kt < 31) {
            const uint32_t noff = (uint32_t)(s ^ 1) << 15;
            #pragma unroll
            for (int it = 0; it < 2; it++) {
                int f = tid + it * 256;
                int row = f >> 2, grp = f & 3;
                float4 f0 = pf[it][0], f1 = pf[it][1];
                uint4 ah = make_uint4(hi_pack(f0.x, f0.y), hi_pack(f0.z, f0.w),
                                      hi_pack(f1.x, f1.y), hi_pack(f1.z, f1.w));
                uint4 al = make_uint4(lo_pack(f0.x, f0.y), lo_pack(f0.z, f0.w),
                                      lo_pack(f1.x, f1.y), lo_pack(f1.z, f1.w));
                *(uint4*)(smx + noff + row * 128 + ((grp ^ (row & 7)) << 4)) = ah;
                *(uint4*)(smx + noff + row * 128 + (((grp + 4) ^ (row & 7)) << 4)) = al;
            }
            CP_WAIT0();
        }
        __syncthreads();
    }

    const int g = lane >> 2, tg = lane & 3;
    #pragma unroll
    for (int i = 0; i < 4; i++) {
        const int r0 = brow + wm + i * 16 + g;
        #pragma unroll
        for (int j = 0; j < 4; j++) {
            const int col = bcol + wn + j * 8 + tg * 2;
            float2 bb = *(const float2*)(bias + col);
            float2 o0 = make_float2(acc[i][j][0] + bb.x, acc[i][j][1] + bb.y);
            float2 o1 = make_float2(acc[i][j][2] + bb.x, acc[i][j][3] + bb.y);
            *(float2*)(C + (size_t)r0 * DMODEL + col)       = o0;
            *(float2*)(C + (size_t)(r0 + 8) * DMODEL + col) = o1;
        }
    }
}

__global__ __launch_bounds__(256, 2)
void gemm_mma_qkv(GemmJob job) {
    const int z = blockIdx.z;
    gemm_mma_body(job.A[z], job.Bh[z], job.Bl[z], job.bias[z], job.C[z]);
}

__global__ __launch_bounds__(256, 2)
void gemm_mma_one(const float* __restrict__ A, const __nv_bfloat16* __restrict__ Bh,
                  const __nv_bfloat16* __restrict__ Bl, const float* __restrict__ bias,
                  float* __restrict__ C) {
    gemm_mma_body(A, Bh, Bl, bias, C);
}

// ==================== HMMA sliding-window attention ====================
#define SQH 0
#define SQL 8192
#define SKH 16384
#define SKL 32768
#define SVH 49152
#define SVL 65536
#define SMP 81920
#define SLP 82432
#define ATTN_SMEM_B 83968

__device__ __forceinline__
void load_seq128(const float* __restrict__ src, char* dh, char* dl,
                 int b, int h, int kbase, int hi_idx, int tid) {
    #pragma unroll
    for (int it = 0; it < 4; it++) {
        int f = tid + it * 256;
        int r = f >> 3, gr = f & 7;
        int kr = kbase + r;
        float4 f0 = make_float4(0.f, 0.f, 0.f, 0.f), f1 = f0;
        if (kr <= hi_idx) {
            const float* p = src + ((size_t)(b * SEQ + kr)) * DMODEL + h * DK + gr * 8;
            f0 = *(const float4*)p;
            f1 = *(const float4*)(p + 4);
        }
        uint4 hh = make_uint4(hi_pack(f0.x, f0.y), hi_pack(f0.z, f0.w),
                              hi_pack(f1.x, f1.y), hi_pack(f1.z, f1.w));
        uint4 ll = make_uint4(lo_pack(f0.x, f0.y), lo_pack(f0.z, f0.w),
                              lo_pack(f1.x, f1.y), lo_pack(f1.z, f1.w));
        int off = r * 128 + ((gr ^ (r & 7)) << 4);
        *(uint4*)(dh + off) = hh;
        *(uint4*)(dl + off) = ll;
    }
}

// QK^T for this warp's 16 q-rows x 64-key half -> acc[8][4]
__device__ __forceinline__
void qk_mma(float acc[8][4], uint32_t qh, uint32_t ql, uint32_t kh, uint32_t kl,
            int wm, int wnh, int lane) {
    #pragma unroll
    for (int j = 0; j < 8; j++)
        #pragma unroll
        for (int u = 0; u < 4; u++) acc[j][u] = 0.f;
    #pragma unroll
    for (int ks = 0; ks < 4; ks++) {
        uint32_t aH[4], aL[4];
        int ar = wm + (lane & 15);
        int cA = ks * 2 + (lane >> 4);
        uint32_t aoff = ar * 128 + ((cA ^ (ar & 7)) << 4);
        ldmx4(aH, qh + aoff);
        ldmx4(aL, ql + aoff);
        int cB = ks * 2 + ((lane >> 3) & 1);
        #pragma unroll
        for (int jp = 0; jp < 4; jp++) {
            int rn = wnh * 64 + jp * 16 + (lane & 7) + ((lane >> 4) & 1) * 8;
            uint32_t boff = rn * 128 + ((cB ^ (rn & 7)) << 4);
            uint32_t bh4[4], bl4[4];
            ldmx4(bh4, kh + boff);
            ldmx4(bl4, kl + boff);
            mma_bf16(acc[jp * 2], aH, bh4);
            mma_bf16(acc[jp * 2], aH, bl4);
            mma_bf16(acc[jp * 2], aL, bh4);
            mma_bf16(acc[jp * 2 + 1], aH, bh4 + 2);
            mma_bf16(acc[jp * 2 + 1], aH, bl4 + 2);
            mma_bf16(acc[jp * 2 + 1], aL, bh4 + 2);
        }
    }
}

__global__ __launch_bounds__(256, 2)
void attn_mma(float* __restrict__ attnp) {
    extern __shared__ char sax[];
    float* sMp = (float*)(sax + SMP);
    float* sLp = (float*)(sax + SLP);

    const int qt = blockIdx.x, h = blockIdx.y, b = blockIdx.z;
    const int q0 = qt * 64;
    const int tid = threadIdx.x, lane = tid & 31, w = tid >> 5;
    const int wm = (w >> 1) << 4;
    const int wnh = w & 1;
    const int g = lane >> 2, tg = lane & 3;

    const int lo  = max(0, q0 - WIN);
    const int hi  = min(SEQ - 1, q0 + 63 + WIN);
    const int cnt = hi - lo + 1;
    const int nch = (cnt + 127) >> 7;

    const uint32_t qh = s2u(sax) + SQH, ql = s2u(sax) + SQL;
    const uint32_t kh = s2u(sax) + SKH, kl = s2u(sax) + SKL;
    const uint32_t vh = s2u(sax) + SVH, vl = s2u(sax) + SVL;

    {
        const float* qb = g_q + ((size_t)(b * SEQ + q0)) * DMODEL + h * DK;
        #pragma unroll
        for (int it = 0; it < 2; it++) {
            int f = tid + it * 256;
            int r = f >> 3, gr = f & 7;
            const float* p = qb + (size_t)r * DMODEL + gr * 8;
            float4 f0 = *(const float4*)p, f1 = *(const float4*)(p + 4);
            uint4 hh = make_uint4(hi_pack(f0.x, f0.y), hi_pack(f0.z, f0.w),
                                  hi_pack(f1.x, f1.y), hi_pack(f1.z, f1.w));
            uint4 ll = make_uint4(lo_pack(f0.x, f0.y), lo_pack(f0.z, f0.w),
                                  lo_pack(f1.x, f1.y), lo_pack(f1.z, f1.w));
            int off = r * 128 + ((gr ^ (r & 7)) << 4);
            *(uint4*)(sax + SQH + off) = hh;
            *(uint4*)(sax + SQL + off) = ll;
        }
    }

    const int qg0 = q0 + wm + g, qg1 = qg0 + 8;
    const int jlo0 = max(lo, qg0 - WIN), jhi0 = min(hi, qg0 + WIN);
    const int jlo1 = max(lo, qg1 - WIN), jhi1 = min(hi, qg1 + WIN);

    // ---- pass 1: online (m, l) ----
    float m0 = -1e30f, m1 = -1e30f, l0 = 0.f, l1 = 0.f;
    for (int c = 0; c < nch; c++) {
        __syncthreads();
        load_seq128(g_k, sax + SKH, sax + SKL, b, h, lo + c * 128, hi, tid);
        __syncthreads();
        float acc[8][4];
        qk_mma(acc, qh, ql, kh, kl, wm, wnh, lane);

        const int cb = lo + c * 128 + wnh * 64;
        float cmax0 = -1e30f, cmax1 = -1e30f;
        #pragma unroll
        for (int j = 0; j < 8; j++) {
            int jg = cb + j * 8 + tg * 2;
            #pragma unroll
            for (int u = 0; u < 4; u++) acc[j][u] *= 0.125f;
            if (jg     >= jlo0 && jg     <= jhi0) cmax0 = fmaxf(cmax0, acc[j][0]);
            if (jg + 1 >= jlo0 && jg + 1 <= jhi0) cmax0 = fmaxf(cmax0, acc[j][1]);
            if (jg     >= jlo1 && jg     <= jhi1) cmax1 = fmaxf(cmax1, acc[j][2]);
            if (jg + 1 >= jlo1 && jg + 1 <= jhi1) cmax1 = fmaxf(cmax1, acc[j][3]);
        }
        cmax0 = fmaxf(cmax0, __shfl_xor_sync(0xffffffffu, cmax0, 1));
        cmax0 = fmaxf(cmax0, __shfl_xor_sync(0xffffffffu, cmax0, 2));
        cmax1 = fmaxf(cmax1, __shfl_xor_sync(0xffffffffu, cmax1, 1));
        cmax1 = fmaxf(cmax1, __shfl_xor_sync(0xffffffffu, cmax1, 2));

        float mn0 = fmaxf(m0, cmax0), mn1 = fmaxf(m1, cmax1);
        float s0 = 0.f, s1 = 0.f;
        #pragma unroll
        for (int j = 0; j < 8; j++) {
            int jg = cb + j * 8 + tg * 2;
            if (jg     >= jlo0 && jg     <= jhi0) s0 += __expf(acc[j][0] - mn0);
            if (jg + 1 >= jlo0 && jg + 1 <= jhi0) s0 += __expf(acc[j][1] - mn0);
            if (jg     >= jlo1 && jg     <= jhi1) s1 += __expf(acc[j][2] - mn1);
            if (jg + 1 >= jlo1 && jg + 1 <= jhi1) s1 += __expf(acc[j][3] - mn1);
        }
        s0 += __shfl_xor_sync(0xffffffffu, s0, 1);
        s0 += __shfl_xor_sync(0xffffffffu, s0, 2);
        s1 += __shfl_xor_sync(0xffffffffu, s1, 1);
        s1 += __shfl_xor_sync(0xffffffffu, s1, 2);

        l0 = (m0 > -1e29f ? l0 * __expf(m0 - mn0) : 0.f) + s0;
        l1 = (m1 > -1e29f ? l1 * __expf(m1 - mn1) : 0.f) + s1;
        m0 = mn0; m1 = mn1;
    }

    if (tg == 0) {
        sMp[wnh * 64 + wm + g]     = m0;  sLp[wnh * 64 + wm + g]     = l0;
        sMp[wnh * 64 + wm + g + 8] = m1;  sLp[wnh * 64 + wm + g + 8] = l1;
    }
    __syncthreads();
    float mf0, mf1, li0, li1;
    {
        int r0 = wm + g, r1 = r0 + 8;
        float ma = sMp[r0], mb2 = sMp[64 + r0];
        float la = sLp[r0], lb2 = sLp[64 + r0];
        mf0 = fmaxf(ma, mb2);
        li0 = 1.f / (la * __expf(ma - mf0) + lb2 * __expf(mb2 - mf0));
        ma = sMp[r1]; mb2 = sMp[64 + r1];
        la = sLp[r1]; lb2 = sLp[64 + r1];
        mf1 = fmaxf(ma, mb2);
        li1 = 1.f / (la * __expf(ma - mf1) + lb2 * __expf(mb2 - mf1));
    }

    float* baseA = nullptr;
    if (attnp) {
        baseA = attnp + ((size_t)((b * NHEADS + h) * SEQ + q0)) * SEQ;
        const int z2 = min((int)SEQ, lo + nch * 128);
        for (int f = tid; f < 64 * 512; f += 256) {
            int m = f >> 9, c4 = (f & 511) << 2;
            if (c4 < lo || c4 >= z2)
                *(float4*)(baseA + (size_t)m * SEQ + c4) = make_float4(0.f, 0.f, 0.f, 0.f);
        }
    }

    // ---- pass 2 ----
    float oacc[4][4];
    #pragma unroll
    for (int j = 0; j < 4; j++)
        #pragma unroll
        for (int u = 0; u < 4; u++) oacc[j][u] = 0.f;

    for (int c = 0; c < nch; c++) {
        __syncthreads();
        load_seq128(g_k, sax + SKH, sax + SKL, b, h, lo + c * 128, hi, tid);
        load_seq128(g_v, sax + SVH, sax + SVL, b, h, lo + c * 128, hi, tid);
        __syncthreads();
        float acc[8][4];
        qk_mma(acc, qh, ql, kh, kl, wm, wnh, lane);

        const int cb = lo + c * 128 + wnh * 64;
        #pragma unroll
        for (int j = 0; j < 8; j++) {
            int jg = cb + j * 8 + tg * 2;
            float p0 = (jg     >= jlo0 && jg     <= jhi0) ? __expf(acc[j][0] * 0.125f - mf0) * li0 : 0.f;
            float p1 = (jg + 1 >= jlo0 && jg + 1 <= jhi0) ? __expf(acc[j][1] * 0.125f - mf0) * li0 : 0.f;
            float p2 = (jg     >= jlo1 && jg     <= jhi1) ? __expf(acc[j][2] * 0.125f - mf1) * li1 : 0.f;
            float p3 = (jg + 1 >= jlo1 && jg + 1 <= jhi1) ? __expf(acc[j][3] * 0.125f - mf1) * li1 : 0.f;
            acc[j][0] = p0; acc[j][1] = p1; acc[j][2] = p2; acc[j][3] = p3;
            if (baseA && jg < SEQ) {
                *(float2*)(baseA + (size_t)(wm + g) * SEQ + jg)     = make_float2(p0, p1);
                *(float2*)(baseA + (size_t)(wm + g + 8) * SEQ + jg) = make_float2(p2, p3);
            }
        }
        __syncthreads();

        #pragma unroll
        for (int j = 0; j < 8; j++) {
            int col = wnh * 64 + j * 8 + tg * 2;
            int sub = col >> 6, c64 = col & 63;
            int r0 = wm + g, r1 = r0 + 8;
            int o0 = sub * 8192 + r0 * 128 + ((((c64 >> 3)) ^ (r0 & 7)) << 4) + (c64 & 7) * 2;
            int o1 = sub * 8192 + r1 * 128 + ((((c64 >> 3)) ^ (r1 & 7)) << 4) + (c64 & 7) * 2;
            *(uint32_t*)(sax + SKH + o0) = hi_pack(acc[j][0], acc[j][1]);
            *(uint32_t*)(sax + SKL + o0) = lo_pack(acc[j][0], acc[j][1]);
            *(uint32_t*)(sax + SKH + o1) = hi_pack(acc[j][2], acc[j][3]);
            *(uint32_t*)(sax + SKL + o1) = lo_pack(acc[j][2], acc[j][3]);
        }
        __syncthreads();

        // AV: A = P [16 q x 128 keys], B = V^T via ldmatrix.x4.trans (d-pairs)
        #pragma unroll
        for (int ks = 0; ks < 8; ks++) {
            uint32_t aH[4], aL[4];
            int ar = wm + (lane & 15);
            int sub = ks >> 2;
            int cA = (ks & 3) * 2 + (lane >> 4);
            uint32_t aoff = sub * 8192 + ar * 128 + ((cA ^ (ar & 7)) << 4);
            ldmx4(aH, kh + aoff);
            ldmx4(aL, kl + aoff);
            #pragma unroll
            for (int jp = 0; jp < 2; jp++) {
                int rv = ks * 16 + (lane & 15);
                int gd = wnh * 4 + jp * 2 + (lane >> 4);
                uint32_t boff = rv * 128 + ((gd ^ (rv & 7)) << 4);
                uint32_t vh4[4], vl4[4];
                ldmx4t(vh4, vh + boff);
                ldmx4t(vl4, vl + boff);
                mma_bf16(oacc[jp * 2], aH, vh4);
                mma_bf16(oacc[jp * 2], aH, vl4);
                mma_bf16(oacc[jp * 2], aL, vh4);
                mma_bf16(oacc[jp * 2 + 1], aH, vh4 + 2);
                mma_bf16(oacc[jp * 2 + 1], aH, vl4 + 2);
                mma_bf16(oacc[jp * 2 + 1], aL, vh4 + 2);
            }
        }
    }

    {
        float* cb2 = g_ctx + ((size_t)(b * SEQ + q0 + wm + g)) * DMODEL + h * DK + wnh * 32;
        #pragma unroll
        for (int j = 0; j < 4; j++) {
            int col = j * 8 + tg * 2;
            *(float2*)(cb2 + col)              = make_float2(oacc[j][0], oacc[j][1]);
            *(float2*)(cb2 + 8 * DMODEL + col) = make_float2(oacc[j][2], oacc[j][3]);
        }
    }
}

// ==================== launch ====================
extern "C" void kernel_launch(void* const* d_in, const int* in_sizes, int n_in,
                              void* d_out, int out_size) {
    const float* q  = (const float*)d_in[0];
    const float* k  = (const float*)d_in[1];
    const float* v  = (const float*)d_in[2];
    const float* Wq = (const float*)d_in[3];
    const float* bq = (const float*)d_in[4];
    const float* Wk = (const float*)d_in[5];
    const float* bk = (const float*)d_in[6];
    const float* Wv = (const float*)d_in[7];
    const float* bv = (const float*)d_in[8];
    const float* Wo = (const float*)d_in[9];
    const float* bo = (const float*)d_in[10];

    float *gq, *gk, *gv, *gctx;
    __nv_bfloat16 *wth, *wtl;
    cudaGetSymbolAddress((void**)&gq,   g_q);
    cudaGetSymbolAddress((void**)&gk,   g_k);
    cudaGetSymbolAddress((void**)&gv,   g_v);
    cudaGetSymbolAddress((void**)&gctx, g_ctx);
    cudaGetSymbolAddress((void**)&wth,  g_wt_hi);
    cudaGetSymbolAddress((void**)&wtl,  g_wt_lo);

    const int GEMM_SMEM = 2 * 32768;
    cudaFuncSetAttribute(gemm_mma_qkv, cudaFuncAttributeMaxDynamicSharedMemorySize, GEMM_SMEM);
    cudaFuncSetAttribute(gemm_mma_one, cudaFuncAttributeMaxDynamicSharedMemorySize, GEMM_SMEM);
    cudaFuncSetAttribute(attn_mma, cudaFuncAttributeMaxDynamicSharedMemorySize, ATTN_SMEM_B);

    WPrep wp;
    wp.w[0] = Wq; wp.w[1] = Wk; wp.w[2] = Wv; wp.w[3] = Wo;
    dim3 pgrid(DMODEL / 32, DMODEL / 32, 4);
    prep_w<<<pgrid, 256>>>(wp, wth, wtl);

    GemmJob job;
    job.A[0] = q;  job.A[1] = k;  job.A[2] = v;
    const size_t WSZ = (size_t)DMODEL * DMODEL;
    job.Bh[0] = wth;           job.Bl[0] = wtl;
    job.Bh[1] = wth + WSZ;     job.Bl[1] = wtl + WSZ;
    job.Bh[2] = wth + 2 * WSZ; job.Bl[2] = wtl + 2 * WSZ;
    job.bias[0] = bq; job.bias[1] = bk; job.bias[2] = bv;
    job.C[0] = gq; job.C[1] = gk; job.C[2] = gv;

    dim3 ggrid(DMODEL / 128, (BATCH * SEQ) / 128, 3);
    gemm_mma_qkv<<<ggrid, 256, GEMM_SMEM>>>(job);

    const size_t OUTE  = (size_t)BATCH * SEQ * DMODEL;
    const size_t ATTNE = (size_t)BATCH * NHEADS * SEQ * SEQ;
    float* outp  = (float*)d_out;
    float* attnp = ((size_t)out_size >= OUTE + ATTNE) ? (outp + OUTE) : nullptr;

    dim3 agrid(SEQ / 64, NHEADS, BATCH);
    attn_mma<<<agrid, 256, ATTN_SMEM_B>>>(attnp);

    dim3 ogrid(DMODEL / 128, (BATCH * SEQ) / 128);
    gemm_mma_one<<<ogrid, 256, GEMM_SMEM>>>(gctx, wth + 3 * WSZ, wtl + 3 * WSZ, bo, outp);
}